// round 8
// baseline (speedup 1.0000x reference)
#include <cuda_runtime.h>
#include <cuda_bf16.h>
#include <math.h>
#include <stdint.h>

typedef unsigned long long ull;
typedef long long ll;

#define TT    2048
#define NH    32
#define NKV   8
#define HD    128
#define NSALT 512
#define NSEG  4
#define SMAXK 512
#define SCALE_F 0.08838834764831845f
#define SCALE_L2E 0.12751742788f   /* SCALE_F * log2(e) */

#define CVT_BLKS 10240
#define VN_BLKS  512
#define VD_BLKS  128

// k_pv smem layout (96KB): A_hi:[0,16K) A_lo:[16K,32K) B_hi:[32K,64K) B_lo:[64K,96K)
#define A_LO 16384u
#define B_HI 32768u
#define B_LO 32768u   // relative to B_HI base (k_pv, 128-row B)

// ---------------- scratch (device globals: allocation-free) ----------------
__device__ float g_inv[(size_t)TT * NH];
__device__ __nv_bfloat16 g_qhi[(size_t)TT * NH * HD];
__device__ __nv_bfloat16 g_qlo[(size_t)TT * NH * HD];
__device__ __nv_bfloat16 g_khi[(size_t)TT * NKV * HD];
__device__ __nv_bfloat16 g_klo[(size_t)TT * NKV * HD];
__device__ __nv_bfloat16 g_Psal_hi[(size_t)TT * NH * 128];
__device__ __nv_bfloat16 g_Psal_lo[(size_t)TT * NH * 128];
__device__ __nv_bfloat16 g_Posal_hi[(size_t)NSALT * NH * SMAXK];
__device__ __nv_bfloat16 g_Posal_lo[(size_t)NSALT * NH * SMAXK];
__device__ __nv_bfloat16 g_vnT_hi[(size_t)NKV * HD * TT];
__device__ __nv_bfloat16 g_vnT_lo[(size_t)NKV * HD * TT];
__device__ __nv_bfloat16 g_vdT_hi[(size_t)NKV * HD * NSALT];
__device__ __nv_bfloat16 g_vdT_lo[(size_t)NKV * HD * NSALT];
__device__ int   g_idx[NSALT];
__device__ int   g_cu[NSEG + 1];
__device__ int   g_salpos[TT];
__device__ int   g_salst[NSEG];
__device__ int   g_salcnt[NSEG];

// ---------------- helpers ----------------
__device__ __forceinline__ uint32_t smem_to_u32(const void* p) {
    uint32_t a;
    asm("{ .reg .u64 t; cvta.to.shared.u64 t, %1; cvt.u32.u64 %0, t; }" : "=r"(a) : "l"(p));
    return a;
}
__device__ __forceinline__ void ldsm4(uint32_t* r, uint32_t addr) {
    asm volatile("ldmatrix.sync.aligned.m8n8.x4.shared.b16 {%0,%1,%2,%3}, [%4];"
        : "=r"(r[0]), "=r"(r[1]), "=r"(r[2]), "=r"(r[3]) : "r"(addr));
}
__device__ __forceinline__ void mma16816(float* c, const uint32_t* a, uint32_t b0, uint32_t b1) {
    asm volatile("mma.sync.aligned.m16n8k16.row.col.f32.bf16.bf16.f32 "
        "{%0,%1,%2,%3}, {%4,%5,%6,%7}, {%8,%9}, {%0,%1,%2,%3};"
        : "+f"(c[0]), "+f"(c[1]), "+f"(c[2]), "+f"(c[3])
        : "r"(a[0]), "r"(a[1]), "r"(a[2]), "r"(a[3]), "r"(b0), "r"(b1));
}
__device__ __forceinline__ void cpa16(uint32_t dst, const void* src, bool valid) {
    int sz = valid ? 16 : 0;
    asm volatile("cp.async.cg.shared.global [%0], [%1], 16, %2;"
        :: "r"(dst), "l"(src), "r"(sz) : "memory");
}
#define CP_COMMIT() asm volatile("cp.async.commit_group;" ::: "memory")
#define CP_WAIT0()  asm volatile("cp.async.wait_group 0;" ::: "memory")
#define CP_WAIT1()  asm volatile("cp.async.wait_group 1;" ::: "memory")

__device__ __forceinline__ float fexp2(float x) {
    float r;
    asm("ex2.approx.f32 %0, %1;" : "=f"(r) : "f"(x));
    return r;
}

// 64(m)x128(n)x128(k) 3-pass HMMA tile (k_pv). Rows 256B, 16B-chunk XOR swizzle.
__device__ __forceinline__ void hmma_tile64(uint32_t sb, float acc[2][4][4], int wid, int lane) {
    const int wm = wid >> 2, wn = wid & 3;
    uint32_t a_ad[2], a_rx[2];
#pragma unroll
    for (int mf = 0; mf < 2; mf++) {
        int row = wm * 32 + mf * 16 + (lane & 15);
        a_ad[mf] = sb + row * 256;
        a_rx[mf] = ((uint32_t)(row & 7)) << 4;
    }
    const int achunk = (lane >> 4);
    uint32_t b_ad[2], b_rx[2];
#pragma unroll
    for (int bg = 0; bg < 2; bg++) {
        int n = wn * 32 + bg * 16 + (lane & 7) + ((lane >> 4) << 3);
        b_ad[bg] = sb + B_HI + n * 256;
        b_rx[bg] = ((uint32_t)(n & 7)) << 4;
    }
    const int bchunk = (lane >> 3) & 1;

#pragma unroll
    for (int ks = 0; ks < 8; ks++) {
        uint32_t ah[2][4], al[2][4];
#pragma unroll
        for (int mf = 0; mf < 2; mf++) {
            uint32_t coff = (((uint32_t)(ks * 2 + achunk)) << 4) ^ a_rx[mf];
            ldsm4(ah[mf], a_ad[mf] + coff);
            ldsm4(al[mf], a_ad[mf] + A_LO + coff);
        }
        uint32_t bh[2][4], bl[2][4];
#pragma unroll
        for (int bg = 0; bg < 2; bg++) {
            uint32_t coff = (((uint32_t)(ks * 2 + bchunk)) << 4) ^ b_rx[bg];
            ldsm4(bh[bg], b_ad[bg] + coff);
            ldsm4(bl[bg], b_ad[bg] + B_LO + coff);
        }
#pragma unroll
        for (int mf = 0; mf < 2; mf++)
#pragma unroll
            for (int nf = 0; nf < 4; nf++) {
                int bg = nf >> 1, sel = (nf & 1) * 2;
                mma16816(acc[mf][nf], ah[mf], bh[bg][sel], bh[bg][sel + 1]);
                mma16816(acc[mf][nf], ah[mf], bl[bg][sel], bl[bg][sel + 1]);
                mma16816(acc[mf][nf], al[mf], bh[bg][sel], bh[bg][sel + 1]);
            }
    }
}

// 64(m)x64(n)x128(k) 3-pass HMMA tile (k_qk). A: hi@0, lo@16K. B: hi@bOff, lo@bOff+16K.
__device__ __forceinline__ void hmma_64(uint32_t sb, uint32_t bOff, float acc[2][2][4],
                                        int wid, int lane) {
    const int wm = wid >> 2, wn = wid & 3;
    uint32_t a_ad[2], a_rx[2];
#pragma unroll
    for (int mf = 0; mf < 2; mf++) {
        int row = wm * 32 + mf * 16 + (lane & 15);
        a_ad[mf] = sb + row * 256;
        a_rx[mf] = ((uint32_t)(row & 7)) << 4;
    }
    const int achunk = (lane >> 4);
    int n = wn * 16 + (lane & 7) + ((lane >> 4) << 3);
    uint32_t b_ad = sb + bOff + n * 256;
    uint32_t b_rx = ((uint32_t)(n & 7)) << 4;
    const int bchunk = (lane >> 3) & 1;

#pragma unroll
    for (int ks = 0; ks < 8; ks++) {
        uint32_t ah[2][4], al[2][4];
#pragma unroll
        for (int mf = 0; mf < 2; mf++) {
            uint32_t coff = (((uint32_t)(ks * 2 + achunk)) << 4) ^ a_rx[mf];
            ldsm4(ah[mf], a_ad[mf] + coff);
            ldsm4(al[mf], a_ad[mf] + A_LO + coff);
        }
        uint32_t bh[4], bl[4];
        {
            uint32_t coff = (((uint32_t)(ks * 2 + bchunk)) << 4) ^ b_rx;
            ldsm4(bh, b_ad + coff);
            ldsm4(bl, b_ad + 16384u + coff);
        }
#pragma unroll
        for (int mf = 0; mf < 2; mf++)
#pragma unroll
            for (int nf = 0; nf < 2; nf++) {
                int sel = nf * 2;
                mma16816(acc[mf][nf], ah[mf], bh[sel], bh[sel + 1]);
                mma16816(acc[mf][nf], ah[mf], bl[sel], bl[sel + 1]);
                mma16816(acc[mf][nf], al[mf], bh[sel], bh[sel + 1]);
            }
    }
}

__device__ __forceinline__ void bf_split(float x, __nv_bfloat16& h, __nv_bfloat16& l) {
    h = __float2bfloat16(x);
    l = __float2bfloat16(x - __bfloat162float(h));
}

// ---------------- K0a: decode indices, segment tables ----------------
__global__ void k_prep(const void* idx_raw, const void* cu_raw) {
    const int* i32 = (const int*)idx_raw;
    const int* c32 = (const int*)cu_raw;
    const bool idx64 = (i32[1] == 0);
    const bool cu64  = (c32[1] == 0);
    const int t = threadIdx.x;

    for (int i = t; i < NSALT; i += 256)
        g_idx[i] = idx64 ? (int)((const long long*)idx_raw)[i] : i32[i];
    if (t <= NSEG)
        g_cu[t] = cu64 ? (int)((const long long*)cu_raw)[t] : c32[t];
    for (int i = t; i < TT; i += 256) g_salpos[i] = -1;
    __syncthreads();
    for (int i = t; i < NSALT; i += 256) g_salpos[g_idx[i]] = i;
    if (t == 0) {
        for (int s = 0; s < NSEG; s++) {
            int a = 0;
            while (a < NSALT && g_idx[a] < g_cu[s]) a++;
            int b = a;
            while (b < NSALT && g_idx[b] < g_cu[s + 1]) b++;
            g_salst[s] = a;
            g_salcnt[s] = b - a;
        }
    }
}

// ---------------- K0b (merged): cvt || build_vn || build_vd ----------------
__global__ void __launch_bounds__(256) k_pre(const float* __restrict__ q, const float* __restrict__ kk,
                                             const float* __restrict__ v, const float* __restrict__ vc) {
    extern __shared__ float tile[];   // [32][129]
    const int bx = blockIdx.x;
    const int tid = threadIdx.x;

    if (bx < CVT_BLKS) {
        const int nq4 = TT * NH * HD / 4;
        int i = bx * 256 + tid;
        float4 x;
        __nv_bfloat162 *h2, *l2;
        if (i < nq4) {
            x = ((const float4*)q)[i];
            h2 = (__nv_bfloat162*)g_qhi + 2 * (size_t)i;
            l2 = (__nv_bfloat162*)g_qlo + 2 * (size_t)i;
        } else {
            int j = i - nq4;
            x = ((const float4*)kk)[j];
            h2 = (__nv_bfloat162*)g_khi + 2 * (size_t)j;
            l2 = (__nv_bfloat162*)g_klo + 2 * (size_t)j;
        }
        __nv_bfloat162 a = __float22bfloat162_rn(make_float2(x.x, x.y));
        __nv_bfloat162 b = __float22bfloat162_rn(make_float2(x.z, x.w));
        __nv_bfloat162 al = __float22bfloat162_rn(make_float2(x.x - __low2float(a), x.y - __high2float(a)));
        __nv_bfloat162 bl = __float22bfloat162_rn(make_float2(x.z - __low2float(b), x.w - __high2float(b)));
        h2[0] = a; h2[1] = b; l2[0] = al; l2[1] = bl;
        return;
    }

    if (bx < CVT_BLKS + VN_BLKS) {
        int t2 = bx - CVT_BLKS;
        int kc = t2 >> 3, g = t2 & 7;
#pragma unroll
        for (int it = 0; it < 4; it++) {
            int fi = tid + it * 256;
            int key = fi >> 5, c4 = fi & 31;
            int gk = kc * 32 + key;
            int sp = g_salpos[gk];
            const float* src = (sp >= 0) ? v + ((size_t)sp * NKV + g) * HD + c4 * 4
                                         : vc + ((size_t)gk * NKV + g) * HD + c4 * 4;
            float4 x = *(const float4*)src;
            float* tr = tile + key * 129 + c4 * 4;
            tr[0] = x.x; tr[1] = x.y; tr[2] = x.z; tr[3] = x.w;
        }
        __syncthreads();
#pragma unroll
        for (int it = 0; it < 8; it++) {
            int wi = tid + it * 256;
            int d = wi >> 4, kp = wi & 15;
            float v0 = tile[(2 * kp) * 129 + d], v1 = tile[(2 * kp + 1) * 129 + d];
            __nv_bfloat16 h0, l0, h1, l1;
            bf_split(v0, h0, l0); bf_split(v1, h1, l1);
            __nv_bfloat162 ph; ph.x = h0; ph.y = h1;
            __nv_bfloat162 pl; pl.x = l0; pl.y = l1;
            size_t dst = ((size_t)g * HD + d) * TT + kc * 32 + 2 * kp;
            *(__nv_bfloat162*)(g_vnT_hi + dst) = ph;
            *(__nv_bfloat162*)(g_vnT_lo + dst) = pl;
        }
        return;
    }

    {
        int t2 = bx - CVT_BLKS - VN_BLKS;
        int kc = t2 >> 3, g = t2 & 7;
#pragma unroll
        for (int it = 0; it < 4; it++) {
            int fi = tid + it * 256;
            int sidx = fi >> 5, c4 = fi & 31;
            int sal = kc * 32 + sidx;
            const float* pv = v  + ((size_t)sal * NKV + g) * HD + c4 * 4;
            const float* pc = vc + ((size_t)g_idx[sal] * NKV + g) * HD + c4 * 4;
            float4 a = *(const float4*)pv;
            float4 b = *(const float4*)pc;
            float* tr = tile + sidx * 129 + c4 * 4;
            tr[0] = a.x - b.x; tr[1] = a.y - b.y; tr[2] = a.z - b.z; tr[3] = a.w - b.w;
        }
        __syncthreads();
#pragma unroll
        for (int it = 0; it < 8; it++) {
            int wi = tid + it * 256;
            int d = wi >> 4, kp = wi & 15;
            float v0 = tile[(2 * kp) * 129 + d], v1 = tile[(2 * kp + 1) * 129 + d];
            __nv_bfloat16 h0, l0, h1, l1;
            bf_split(v0, h0, l0); bf_split(v1, h1, l1);
            __nv_bfloat162 ph; ph.x = h0; ph.y = h1;
            __nv_bfloat162 pl; pl.x = l0; pl.y = l1;
            size_t dst = ((size_t)g * HD + d) * NSALT + kc * 32 + 2 * kp;
            *(__nv_bfloat162*)(g_vdT_hi + dst) = ph;
            *(__nv_bfloat162*)(g_vdT_lo + dst) = pl;
        }
    }
}

// ---------------- K1: fused QK^T + exp + rowsum, 64x64 tiles, double-buffered ----------------
__device__ __forceinline__ void qk_loadB64(uint32_t sb, uint32_t bOff, int tid, int nt,
                                           int s0, int L, int g) {
#pragma unroll
    for (int it = 0; it < 4; it++) {
        int idx = tid + it * 256;
        int r = idx >> 4, ch = idx & 15;
        uint32_t d = (uint32_t)(r * 256) + (((uint32_t)(ch ^ (r & 7))) << 4);
        int jg = nt * 64 + r;
        bool v = jg < L;
        size_t o = v ? (((size_t)(s0 + jg) * NKV + g) * HD + ch * 8) : 0;
        cpa16(sb + bOff + d, g_khi + o, v);
        cpa16(sb + bOff + 16384u + d, g_klo + o, v);
    }
}

__global__ void __launch_bounds__(256, 2) k_qk() {
    extern __shared__ char dsm[];
    __shared__ int s_sp[SMAXK];
    const int sg = blockIdx.y;
    const int s = sg >> 3, g = sg & 7;
    const int s0 = g_cu[s];
    const int L = g_cu[s + 1] - s0;
    const int mBase = blockIdx.x * 64;
    if (mBase >= 4 * L) return;
    const int salst = g_salst[s];

    const int tid = threadIdx.x, wid = tid >> 5, lane = tid & 31;
    const int wm = wid >> 2, wn = wid & 3;
    const uint32_t sb = smem_to_u32(dsm);

    for (int j = tid; j < L; j += 256) {
        int sp = g_salpos[s0 + j];
        s_sp[j] = sp >= 0 ? sp - salst : -1;
    }

    // A tile: 64 rows, hi/lo
#pragma unroll
    for (int it = 0; it < 4; it++) {
        int idx = tid + it * 256;
        int r = idx >> 4, ch = idx & 15;
        uint32_t d = (uint32_t)(r * 256) + (((uint32_t)(ch ^ (r & 7))) << 4);
        int mm = mBase + r, il = mm >> 2, hh = mm & 3;
        bool v = il < L;
        size_t o = v ? (((size_t)(s0 + il) * NH + 4 * g + hh) * HD + ch * 8) : 0;
        cpa16(sb + d, g_qhi + o, v);
        cpa16(sb + A_LO + d, g_qlo + o, v);
    }

    // per-row metadata
    size_t id0[2], id1[2];
    ll pb0[2], pb1[2];
    bool ok0[2], ok1[2];
#pragma unroll
    for (int mf = 0; mf < 2; mf++) {
        int mr0 = mBase + wm * 32 + mf * 16 + (lane >> 2);
        int mr1 = mr0 + 8;
        int il0 = mr0 >> 2, h0 = mr0 & 3;
        int il1 = mr1 >> 2, h1 = mr1 & 3;
        ok0[mf] = il0 < L; ok1[mf] = il1 < L;
        id0[mf] = ok0[mf] ? ((size_t)(s0 + il0) * NH + 4 * g + h0) : 0;
        id1[mf] = ok1[mf] ? ((size_t)(s0 + il1) * NH + 4 * g + h1) : 0;
        int sp0 = ok0[mf] ? g_salpos[s0 + il0] : -1;
        int sp1 = ok1[mf] ? g_salpos[s0 + il1] : -1;
        pb0[mf] = sp0 >= 0 ? ((ll)sp0 * NH + 4 * g + h0) * SMAXK : -1;
        pb1[mf] = sp1 >= 0 ? ((ll)sp1 * NH + 4 * g + h1) * SMAXK : -1;
    }

    // prime pipeline: buffers at 32K and 64K (each: hi 16K + lo 16K)
    qk_loadB64(sb, 32768u, tid, 0, s0, L, g);
    CP_COMMIT();
    qk_loadB64(sb, 65536u, tid, 1, s0, L, g);
    CP_COMMIT();

    float rs0[2] = {0.f, 0.f}, rs1[2] = {0.f, 0.f};

    for (int nt = 0; nt < 8; nt++) {
        if (nt == 7) { CP_WAIT0(); } else { CP_WAIT1(); }
        __syncthreads();

        float acc[2][2][4];
#pragma unroll
        for (int a = 0; a < 2; a++)
#pragma unroll
            for (int b = 0; b < 2; b++)
#pragma unroll
                for (int c = 0; c < 4; c++) acc[a][b][c] = 0.f;

        uint32_t bOff = 32768u + (uint32_t)(nt & 1) * 32768u;
        hmma_64(sb, bOff, acc, wid, lane);
        __syncthreads();
        if (nt < 6) {
            qk_loadB64(sb, bOff, tid, nt + 2, s0, L, g);
            CP_COMMIT();
        }

        // epilogue (loads already in flight)
#pragma unroll
        for (int nf = 0; nf < 2; nf++) {
            int col = nt * 64 + wn * 16 + nf * 8 + (lane & 3) * 2;
            bool c0 = col < L, c1 = col + 1 < L;
            int spa = c0 ? s_sp[col] : -1;
            int spb = c1 ? s_sp[col + 1] : -1;
#pragma unroll
            for (int mf = 0; mf < 2; mf++) {
                float* c = acc[mf][nf];
                float e0 = (ok0[mf] && c0) ? fexp2(c[0] * SCALE_L2E) : 0.f;
                float e1 = (ok0[mf] && c1) ? fexp2(c[1] * SCALE_L2E) : 0.f;
                float e2 = (ok1[mf] && c0) ? fexp2(c[2] * SCALE_L2E) : 0.f;
                float e3 = (ok1[mf] && c1) ? fexp2(c[3] * SCALE_L2E) : 0.f;
                rs0[mf] += e0 + e1;
                rs1[mf] += e2 + e3;

                if (spa >= 0) {
                    if (ok0[mf]) { __nv_bfloat16 h, l; bf_split(e0, h, l);
                        g_Psal_hi[id0[mf] * 128 + spa] = h; g_Psal_lo[id0[mf] * 128 + spa] = l; }
                    if (ok1[mf]) { __nv_bfloat16 h, l; bf_split(e2, h, l);
                        g_Psal_hi[id1[mf] * 128 + spa] = h; g_Psal_lo[id1[mf] * 128 + spa] = l; }
                }
                if (spb >= 0) {
                    if (ok0[mf]) { __nv_bfloat16 h, l; bf_split(e1, h, l);
                        g_Psal_hi[id0[mf] * 128 + spb] = h; g_Psal_lo[id0[mf] * 128 + spb] = l; }
                    if (ok1[mf]) { __nv_bfloat16 h, l; bf_split(e3, h, l);
                        g_Psal_hi[id1[mf] * 128 + spb] = h; g_Psal_lo[id1[mf] * 128 + spb] = l; }
                }
                if (pb0[mf] >= 0 && c0) {
                    __nv_bfloat16 h0, l0, h1, l1;
                    bf_split(e0, h0, l0); bf_split(e1, h1, l1);
                    __nv_bfloat162 ph; ph.x = h0; ph.y = h1;
                    __nv_bfloat162 pl; pl.x = l0; pl.y = l1;
                    *(__nv_bfloat162*)(g_Posal_hi + pb0[mf] + col) = ph;
                    *(__nv_bfloat162*)(g_Posal_lo + pb0[mf] + col) = pl;
                }
                if (pb1[mf] >= 0 && c0) {
                    __nv_bfloat16 h0, l0, h1, l1;
                    bf_split(e2, h0, l0); bf_split(e3, h1, l1);
                    __nv_bfloat162 ph; ph.x = h0; ph.y = h1;
                    __nv_bfloat162 pl; pl.x = l0; pl.y = l1;
                    *(__nv_bfloat162*)(g_Posal_hi + pb1[mf] + col) = ph;
                    *(__nv_bfloat162*)(g_Posal_lo + pb1[mf] + col) = pl;
                }
            }
        }
    }

    // final rowsum reduction -> g_inv (reuse A region)
#pragma unroll
    for (int mf = 0; mf < 2; mf++) {
        rs0[mf] += __shfl_xor_sync(0xffffffffu, rs0[mf], 1);
        rs0[mf] += __shfl_xor_sync(0xffffffffu, rs0[mf], 2);
        rs1[mf] += __shfl_xor_sync(0xffffffffu, rs1[mf], 1);
        rs1[mf] += __shfl_xor_sync(0xffffffffu, rs1[mf], 2);
    }
    __syncthreads();
    float* red = (float*)dsm;
    if ((lane & 3) == 0) {
#pragma unroll
        for (int mf = 0; mf < 2; mf++) {
            int r0 = wm * 32 + mf * 16 + (lane >> 2);
            red[r0 * 4 + wn] = rs0[mf];
            red[(r0 + 8) * 4 + wn] = rs1[mf];
        }
    }
    __syncthreads();
    if (tid < 64) {
        int mm = mBase + tid, il = mm >> 2, h = mm & 3;
        if (il < L) {
            float s4 = red[tid * 4] + red[tid * 4 + 1] + red[tid * 4 + 2] + red[tid * 4 + 3];
            g_inv[(size_t)(s0 + il) * NH + 4 * g + h] = 1.f / s4;
        }
    }
}

// ---------------- K2 (merged): osal (x<8) || delta (x>=8), 64-row tiles ----------------
__global__ void __launch_bounds__(256, 2) k_pv(const float* __restrict__ cc, float* __restrict__ outc) {
    extern __shared__ char dsm[];
    const int sg = blockIdx.y;
    const int s = sg >> 3, g = sg & 7;
    const int s0 = g_cu[s];
    const int L = g_cu[s + 1] - s0;
    const int salst = g_salst[s], salcnt = g_salcnt[s];

    const int tid = threadIdx.x, wid = tid >> 5, lane = tid & 31;
    const int wm = wid >> 2, wn = wid & 3;
    const uint32_t sb = smem_to_u32(dsm);

    float acc[2][4][4];
#pragma unroll
    for (int a = 0; a < 2; a++)
#pragma unroll
        for (int b = 0; b < 4; b++)
#pragma unroll
            for (int c = 0; c < 4; c++) acc[a][b][c] = 0.f;

    if (blockIdx.x < 8) {
        const int mBase = blockIdx.x * 64;
        if (mBase >= 4 * salcnt) return;

        for (int kc = 0; kc * 128 < L; kc++) {
#pragma unroll
            for (int it = 0; it < 4; it++) {
                int idx = tid + it * 256;
                int r = idx >> 4, ch = idx & 15;
                uint32_t d = (uint32_t)(r * 256) + (((uint32_t)(ch ^ (r & 7))) << 4);
                int m = mBase + r, saloc = m >> 2, hh = m & 3;
                int kk = kc * 128 + ch * 8;
                bool va = (saloc < salcnt) && (kk < L);
                size_t ia = va ? (((size_t)(salst + saloc) * NH + 4 * g + hh) * SMAXK + kk) : 0;
                cpa16(sb + d, g_Posal_hi + ia, va);
                cpa16(sb + A_LO + d, g_Posal_lo + ia, va);
            }
#pragma unroll
            for (int it = 0; it < 8; it++) {
                int idx = tid + it * 256;
                int r = idx >> 4, ch = idx & 15;
                uint32_t d = (uint32_t)(r * 256) + (((uint32_t)(ch ^ (r & 7))) << 4);
                int kk = kc * 128 + ch * 8;
                bool vb = (kk < L);
                size_t ib = vb ? (((size_t)(g * HD + r)) * TT + s0 + kk) : 0;
                cpa16(sb + B_HI + d, g_vnT_hi + ib, vb);
                cpa16(sb + B_HI + B_LO + d, g_vnT_lo + ib, vb);
            }
            CP_COMMIT();
            CP_WAIT0();
            __syncthreads();
            hmma_tile64(sb, acc, wid, lane);
            __syncthreads();
        }

#pragma unroll
        for (int mf = 0; mf < 2; mf++) {
            int mr0 = mBase + wm * 32 + mf * 16 + (lane >> 2);
            int mr1 = mr0 + 8;
            int sa0 = mr0 >> 2, h0 = mr0 & 3;
            int sa1 = mr1 >> 2, h1 = mr1 & 3;
            bool ok0 = sa0 < salcnt, ok1 = sa1 < salcnt;
            size_t id0 = 0, id1 = 0;
            float inv0 = 0.f, inv1 = 0.f;
            if (ok0) { id0 = (size_t)g_idx[salst + sa0] * NH + 4 * g + h0; inv0 = g_inv[id0]; }
            if (ok1) { id1 = (size_t)g_idx[salst + sa1] * NH + 4 * g + h1; inv1 = g_inv[id1]; }
#pragma unroll
            for (int nf = 0; nf < 4; nf++) {
                int dcol = wn * 32 + nf * 8 + (lane & 3) * 2;
                float* c = acc[mf][nf];
                if (ok0) *(float2*)(outc + id0 * HD + dcol) = make_float2(inv0 * c[0], inv0 * c[1]);
                if (ok1) *(float2*)(outc + id1 * HD + dcol) = make_float2(inv1 * c[2], inv1 * c[3]);
            }
        }
    } else {
        const int mBase = (blockIdx.x - 8) * 64;
        if (mBase >= 4 * L) return;

#pragma unroll
        for (int it = 0; it < 4; it++) {
            int idx = tid + it * 256;
            int r = idx >> 4, ch = idx & 15;
            uint32_t d = (uint32_t)(r * 256) + (((uint32_t)(ch ^ (r & 7))) << 4);
            int mm = mBase + r, il = mm >> 2, hh = mm & 3;
            bool va = (il < L) && (ch * 8 < salcnt);
            size_t ia = va ? (((size_t)(s0 + il) * NH + 4 * g + hh) * 128 + ch * 8) : 0;
            cpa16(sb + d, g_Psal_hi + ia, va);
            cpa16(sb + A_LO + d, g_Psal_lo + ia, va);
        }
#pragma unroll
        for (int it = 0; it < 8; it++) {
            int idx = tid + it * 256;
            int r = idx >> 4, ch = idx & 15;
            uint32_t d = (uint32_t)(r * 256) + (((uint32_t)(ch ^ (r & 7))) << 4);
            bool vb = (ch * 8 < salcnt);
            size_t ib = vb ? (((size_t)(g * HD + r)) * NSALT + salst + ch * 8) : 0;
            cpa16(sb + B_HI + d, g_vdT_hi + ib, vb);
            cpa16(sb + B_HI + B_LO + d, g_vdT_lo + ib, vb);
        }
        CP_COMMIT();
        CP_WAIT0();
        __syncthreads();
        hmma_tile64(sb, acc, wid, lane);

#pragma unroll
        for (int mf = 0; mf < 2; mf++) {
            int mr0 = mBase + wm * 32 + mf * 16 + (lane >> 2);
            int mr1 = mr0 + 8;
            int il0 = mr0 >> 2, h0 = mr0 & 3;
            int il1 = mr1 >> 2, h1 = mr1 & 3;
            bool ok0 = (il0 < L) && (g_salpos[s0 + il0] < 0);
            bool ok1 = (il1 < L) && (g_salpos[s0 + il1] < 0);
            size_t id0 = (size_t)(s0 + il0) * NH + 4 * g + h0;
            size_t id1 = (size_t)(s0 + il1) * NH + 4 * g + h1;
            float inv0 = ok0 ? g_inv[id0] : 0.f;
            float inv1 = ok1 ? g_inv[id1] : 0.f;
#pragma unroll
            for (int nf = 0; nf < 4; nf++) {
                int dcol = wn * 32 + nf * 8 + (lane & 3) * 2;
                float* c = acc[mf][nf];
                if (ok0) {
                    size_t ob = id0 * HD + dcol;
                    float2 cv = *(const float2*)(cc + ob);
                    *(float2*)(outc + ob) = make_float2(cv.x + inv0 * c[0], cv.y + inv0 * c[1]);
                }
                if (ok1) {
                    size_t ob = id1 * HD + dcol;
                    float2 cv = *(const float2*)(cc + ob);
                    *(float2*)(outc + ob) = make_float2(cv.x + inv1 * c[2], cv.y + inv1 * c[3]);
                }
            }
        }
    }
}

// ---------------- K3: per-row cosine similarity (warp-shuffle reduction) ----------------
__global__ void __launch_bounds__(512) k_cos(const float* __restrict__ cc, const float* __restrict__ outc,
                                             float* __restrict__ cosv) {
    const int tid = threadIdx.x, wid = tid >> 5, lane = tid & 31;
    size_t base = (size_t)blockIdx.x * (NH * HD);
    const float4* a4 = (const float4*)(cc + base);
    const float4* b4 = (const float4*)(outc + base);
    float ab = 0.f, aa = 0.f, bb = 0.f;
#pragma unroll
    for (int j = 0; j < 2; j++) {
        float4 x = a4[tid + j * 512], y = b4[tid + j * 512];
        ab += x.x * y.x + x.y * y.y + x.z * y.z + x.w * y.w;
        aa += x.x * x.x + x.y * x.y + x.z * x.z + x.w * x.w;
        bb += y.x * y.x + y.y * y.y + y.z * y.z + y.w * y.w;
    }
#pragma unroll
    for (int o = 16; o; o >>= 1) {
        ab += __shfl_xor_sync(0xffffffffu, ab, o);
        aa += __shfl_xor_sync(0xffffffffu, aa, o);
        bb += __shfl_xor_sync(0xffffffffu, bb, o);
    }
    __shared__ float sh[3][16];
    if (lane == 0) { sh[0][wid] = ab; sh[1][wid] = aa; sh[2][wid] = bb; }
    __syncthreads();
    if (tid < 32) {
        float a2 = (tid < 16) ? sh[0][tid] : 0.f;
        float b2 = (tid < 16) ? sh[1][tid] : 0.f;
        float c2 = (tid < 16) ? sh[2][tid] : 0.f;
#pragma unroll
        for (int o = 8; o; o >>= 1) {
            a2 += __shfl_xor_sync(0xffffffffu, a2, o);
            b2 += __shfl_xor_sync(0xffffffffu, b2, o);
            c2 += __shfl_xor_sync(0xffffffffu, c2, o);
        }
        if (tid == 0)
            cosv[blockIdx.x] = a2 / (sqrtf(b2) * sqrtf(c2) + 1e-8f);
    }
}

// ---------------- launch ----------------
extern "C" void kernel_launch(void* const* d_in, const int* in_sizes, int n_in,
                              void* d_out, int out_size) {
    const float* q       = (const float*)d_in[0];
    const float* k       = (const float*)d_in[1];
    const float* v       = (const float*)d_in[2];
    const float* v_cache = (const float*)d_in[3];
    const float* c_cache = (const float*)d_in[4];
    const void*  idx     = d_in[5];
    const void*  cu      = d_in[6];

    float* outc = (float*)d_out;
    float* cosv = outc + (size_t)(out_size - TT);

    cudaFuncSetAttribute(k_qk,  cudaFuncAttributeMaxDynamicSharedMemorySize, 98304);
    cudaFuncSetAttribute(k_pv,  cudaFuncAttributeMaxDynamicSharedMemorySize, 98304);
    cudaFuncSetAttribute(k_pre, cudaFuncAttributeMaxDynamicSharedMemorySize, 16512);

    k_prep<<<1, 256>>>(idx, cu);
    k_pre<<<CVT_BLKS + VN_BLKS + VD_BLKS, 256, 16512>>>(q, k, v, v_cache);
    k_qk<<<dim3(32, 32), 256, 98304>>>();
    k_pv<<<dim3(40, 32), 256, 98304>>>(c_cache, outc);
    k_cos<<<TT, 512>>>(c_cache, outc, cosv);
}

// round 9
// speedup vs baseline: 1.0448x; 1.0448x over previous
#include <cuda_runtime.h>
#include <cuda_bf16.h>
#include <math.h>
#include <stdint.h>

typedef unsigned long long ull;
typedef long long ll;

#define TT    2048
#define NH    32
#define NKV   8
#define HD    128
#define NSALT 512
#define NSEG  4
#define SMAXK 512
#define SCALE_F 0.08838834764831845f
#define SCALE_L2E 0.12751742788f   /* SCALE_F * log2(e) */

#define CVT_BLKS 10240
#define VN_BLKS  512
#define VD_BLKS  128

// smem layout (96KB): A_hi:[0,16K) A_lo:[16K,32K) B_hi:[32K,64K) B_lo:[64K,96K)
#define A_LO 16384u
#define B_HI 32768u
#define B_LO 32768u   // relative to B_HI base

// ---------------- scratch (device globals: allocation-free) ----------------
__device__ float g_inv[(size_t)TT * NH];
__device__ __nv_bfloat16 g_qhi[(size_t)TT * NH * HD];
__device__ __nv_bfloat16 g_qlo[(size_t)TT * NH * HD];
__device__ __nv_bfloat16 g_khi[(size_t)TT * NKV * HD];
__device__ __nv_bfloat16 g_klo[(size_t)TT * NKV * HD];
__device__ __nv_bfloat16 g_Psal_hi[(size_t)TT * NH * 128];
__device__ __nv_bfloat16 g_Psal_lo[(size_t)TT * NH * 128];
__device__ __nv_bfloat16 g_Posal_hi[(size_t)NSALT * NH * SMAXK];
__device__ __nv_bfloat16 g_Posal_lo[(size_t)NSALT * NH * SMAXK];
__device__ __nv_bfloat16 g_vnT_hi[(size_t)NKV * HD * TT];
__device__ __nv_bfloat16 g_vnT_lo[(size_t)NKV * HD * TT];
__device__ __nv_bfloat16 g_vdT_hi[(size_t)NKV * HD * NSALT];
__device__ __nv_bfloat16 g_vdT_lo[(size_t)NKV * HD * NSALT];
__device__ int   g_idx[NSALT];
__device__ int   g_cu[NSEG + 1];
__device__ int   g_salpos[TT];
__device__ int   g_salst[NSEG];
__device__ int   g_salcnt[NSEG];

// ---------------- helpers ----------------
__device__ __forceinline__ uint32_t smem_to_u32(const void* p) {
    uint32_t a;
    asm("{ .reg .u64 t; cvta.to.shared.u64 t, %1; cvt.u32.u64 %0, t; }" : "=r"(a) : "l"(p));
    return a;
}
__device__ __forceinline__ void ldsm4(uint32_t* r, uint32_t addr) {
    asm volatile("ldmatrix.sync.aligned.m8n8.x4.shared.b16 {%0,%1,%2,%3}, [%4];"
        : "=r"(r[0]), "=r"(r[1]), "=r"(r[2]), "=r"(r[3]) : "r"(addr));
}
__device__ __forceinline__ void mma16816(float* c, const uint32_t* a, uint32_t b0, uint32_t b1) {
    asm volatile("mma.sync.aligned.m16n8k16.row.col.f32.bf16.bf16.f32 "
        "{%0,%1,%2,%3}, {%4,%5,%6,%7}, {%8,%9}, {%0,%1,%2,%3};"
        : "+f"(c[0]), "+f"(c[1]), "+f"(c[2]), "+f"(c[3])
        : "r"(a[0]), "r"(a[1]), "r"(a[2]), "r"(a[3]), "r"(b0), "r"(b1));
}
__device__ __forceinline__ void cpa16(uint32_t dst, const void* src, bool valid) {
    int sz = valid ? 16 : 0;
    asm volatile("cp.async.cg.shared.global [%0], [%1], 16, %2;"
        :: "r"(dst), "l"(src), "r"(sz) : "memory");
}
#define CP_COMMIT() asm volatile("cp.async.commit_group;" ::: "memory")
#define CP_WAIT0()  asm volatile("cp.async.wait_group 0;" ::: "memory")

__device__ __forceinline__ float fexp2(float x) {
    float r;
    asm("ex2.approx.f32 %0, %1;" : "=f"(r) : "f"(x));
    return r;
}

// 64(m)x128(n)x128(k) bf16 3-pass HMMA tile. Rows 256B, 16B-chunk XOR swizzle.
// 8 warps = 2(m) x 4(n); warp tile 32x32. acc[2][4][4]. (Verified round 4/6.)
__device__ __forceinline__ void hmma_tile64(uint32_t sb, float acc[2][4][4], int wid, int lane) {
    const int wm = wid >> 2, wn = wid & 3;
    uint32_t a_ad[2], a_rx[2];
#pragma unroll
    for (int mf = 0; mf < 2; mf++) {
        int row = wm * 32 + mf * 16 + (lane & 15);
        a_ad[mf] = sb + row * 256;
        a_rx[mf] = ((uint32_t)(row & 7)) << 4;
    }
    const int achunk = (lane >> 4);
    uint32_t b_ad[2], b_rx[2];
#pragma unroll
    for (int bg = 0; bg < 2; bg++) {
        int n = wn * 32 + bg * 16 + (lane & 7) + ((lane >> 4) << 3);
        b_ad[bg] = sb + B_HI + n * 256;
        b_rx[bg] = ((uint32_t)(n & 7)) << 4;
    }
    const int bchunk = (lane >> 3) & 1;

#pragma unroll
    for (int ks = 0; ks < 8; ks++) {
        uint32_t ah[2][4], al[2][4];
#pragma unroll
        for (int mf = 0; mf < 2; mf++) {
            uint32_t coff = (((uint32_t)(ks * 2 + achunk)) << 4) ^ a_rx[mf];
            ldsm4(ah[mf], a_ad[mf] + coff);
            ldsm4(al[mf], a_ad[mf] + A_LO + coff);
        }
        uint32_t bh[2][4], bl[2][4];
#pragma unroll
        for (int bg = 0; bg < 2; bg++) {
            uint32_t coff = (((uint32_t)(ks * 2 + bchunk)) << 4) ^ b_rx[bg];
            ldsm4(bh[bg], b_ad[bg] + coff);
            ldsm4(bl[bg], b_ad[bg] + B_LO + coff);
        }
#pragma unroll
        for (int mf = 0; mf < 2; mf++)
#pragma unroll
            for (int nf = 0; nf < 4; nf++) {
                int bg = nf >> 1, sel = (nf & 1) * 2;
                mma16816(acc[mf][nf], ah[mf], bh[bg][sel], bh[bg][sel + 1]);
                mma16816(acc[mf][nf], ah[mf], bl[bg][sel], bl[bg][sel + 1]);
                mma16816(acc[mf][nf], al[mf], bh[bg][sel], bh[bg][sel + 1]);
            }
    }
}

__device__ __forceinline__ void bf_split(float x, __nv_bfloat16& h, __nv_bfloat16& l) {
    h = __float2bfloat16(x);
    l = __float2bfloat16(x - __bfloat162float(h));
}

// ---------------- K0a: decode indices, segment tables ----------------
__global__ void k_prep(const void* idx_raw, const void* cu_raw) {
    const int* i32 = (const int*)idx_raw;
    const int* c32 = (const int*)cu_raw;
    const bool idx64 = (i32[1] == 0);
    const bool cu64  = (c32[1] == 0);
    const int t = threadIdx.x;

    for (int i = t; i < NSALT; i += 256)
        g_idx[i] = idx64 ? (int)((const long long*)idx_raw)[i] : i32[i];
    if (t <= NSEG)
        g_cu[t] = cu64 ? (int)((const long long*)cu_raw)[t] : c32[t];
    for (int i = t; i < TT; i += 256) g_salpos[i] = -1;
    __syncthreads();
    for (int i = t; i < NSALT; i += 256) g_salpos[g_idx[i]] = i;
    if (t == 0) {
        for (int s = 0; s < NSEG; s++) {
            int a = 0;
            while (a < NSALT && g_idx[a] < g_cu[s]) a++;
            int b = a;
            while (b < NSALT && g_idx[b] < g_cu[s + 1]) b++;
            g_salst[s] = a;
            g_salcnt[s] = b - a;
        }
    }
}

// ---------------- K0b (merged): cvt || build_vn || build_vd ----------------
__global__ void __launch_bounds__(256) k_pre(const float* __restrict__ q, const float* __restrict__ kk,
                                             const float* __restrict__ v, const float* __restrict__ vc) {
    extern __shared__ float tile[];   // [32][129]
    const int bx = blockIdx.x;
    const int tid = threadIdx.x;

    if (bx < CVT_BLKS) {
        const int nq4 = TT * NH * HD / 4;
        int i = bx * 256 + tid;
        float4 x;
        __nv_bfloat162 *h2, *l2;
        if (i < nq4) {
            x = ((const float4*)q)[i];
            h2 = (__nv_bfloat162*)g_qhi + 2 * (size_t)i;
            l2 = (__nv_bfloat162*)g_qlo + 2 * (size_t)i;
        } else {
            int j = i - nq4;
            x = ((const float4*)kk)[j];
            h2 = (__nv_bfloat162*)g_khi + 2 * (size_t)j;
            l2 = (__nv_bfloat162*)g_klo + 2 * (size_t)j;
        }
        __nv_bfloat162 a = __float22bfloat162_rn(make_float2(x.x, x.y));
        __nv_bfloat162 b = __float22bfloat162_rn(make_float2(x.z, x.w));
        __nv_bfloat162 al = __float22bfloat162_rn(make_float2(x.x - __low2float(a), x.y - __high2float(a)));
        __nv_bfloat162 bl = __float22bfloat162_rn(make_float2(x.z - __low2float(b), x.w - __high2float(b)));
        h2[0] = a; h2[1] = b; l2[0] = al; l2[1] = bl;
        return;
    }

    if (bx < CVT_BLKS + VN_BLKS) {
        int t2 = bx - CVT_BLKS;
        int kc = t2 >> 3, g = t2 & 7;
#pragma unroll
        for (int it = 0; it < 4; it++) {
            int fi = tid + it * 256;
            int key = fi >> 5, c4 = fi & 31;
            int gk = kc * 32 + key;
            int sp = g_salpos[gk];
            const float* src = (sp >= 0) ? v + ((size_t)sp * NKV + g) * HD + c4 * 4
                                         : vc + ((size_t)gk * NKV + g) * HD + c4 * 4;
            float4 x = *(const float4*)src;
            float* tr = tile + key * 129 + c4 * 4;
            tr[0] = x.x; tr[1] = x.y; tr[2] = x.z; tr[3] = x.w;
        }
        __syncthreads();
#pragma unroll
        for (int it = 0; it < 8; it++) {
            int wi = tid + it * 256;
            int d = wi >> 4, kp = wi & 15;
            float v0 = tile[(2 * kp) * 129 + d], v1 = tile[(2 * kp + 1) * 129 + d];
            __nv_bfloat16 h0, l0, h1, l1;
            bf_split(v0, h0, l0); bf_split(v1, h1, l1);
            __nv_bfloat162 ph; ph.x = h0; ph.y = h1;
            __nv_bfloat162 pl; pl.x = l0; pl.y = l1;
            size_t dst = ((size_t)g * HD + d) * TT + kc * 32 + 2 * kp;
            *(__nv_bfloat162*)(g_vnT_hi + dst) = ph;
            *(__nv_bfloat162*)(g_vnT_lo + dst) = pl;
        }
        return;
    }

    {
        int t2 = bx - CVT_BLKS - VN_BLKS;
        int kc = t2 >> 3, g = t2 & 7;
#pragma unroll
        for (int it = 0; it < 4; it++) {
            int fi = tid + it * 256;
            int sidx = fi >> 5, c4 = fi & 31;
            int sal = kc * 32 + sidx;
            const float* pv = v  + ((size_t)sal * NKV + g) * HD + c4 * 4;
            const float* pc = vc + ((size_t)g_idx[sal] * NKV + g) * HD + c4 * 4;
            float4 a = *(const float4*)pv;
            float4 b = *(const float4*)pc;
            float* tr = tile + sidx * 129 + c4 * 4;
            tr[0] = a.x - b.x; tr[1] = a.y - b.y; tr[2] = a.z - b.z; tr[3] = a.w - b.w;
        }
        __syncthreads();
#pragma unroll
        for (int it = 0; it < 8; it++) {
            int wi = tid + it * 256;
            int d = wi >> 4, kp = wi & 15;
            float v0 = tile[(2 * kp) * 129 + d], v1 = tile[(2 * kp + 1) * 129 + d];
            __nv_bfloat16 h0, l0, h1, l1;
            bf_split(v0, h0, l0); bf_split(v1, h1, l1);
            __nv_bfloat162 ph; ph.x = h0; ph.y = h1;
            __nv_bfloat162 pl; pl.x = l0; pl.y = l1;
            size_t dst = ((size_t)g * HD + d) * NSALT + kc * 32 + 2 * kp;
            *(__nv_bfloat162*)(g_vdT_hi + dst) = ph;
            *(__nv_bfloat162*)(g_vdT_lo + dst) = pl;
        }
    }
}

// ---------------- K1: fused QK^T + exp + rowsum, 64x128 tiles, prefetch-during-epilogue ----------------
__device__ __forceinline__ void qk_loadB(uint32_t sb, int tid, int nt, int s0, int L, int g) {
#pragma unroll
    for (int it = 0; it < 8; it++) {
        int idx = tid + it * 256;
        int r = idx >> 4, ch = idx & 15;
        uint32_t d = (uint32_t)(r * 256) + (((uint32_t)(ch ^ (r & 7))) << 4);
        int jg = nt * 128 + r;
        bool v = jg < L;
        size_t o = v ? (((size_t)(s0 + jg) * NKV + g) * HD + ch * 8) : 0;
        cpa16(sb + B_HI + d, g_khi + o, v);
        cpa16(sb + B_HI + B_LO + d, g_klo + o, v);
    }
}

__global__ void __launch_bounds__(256, 2) k_qk() {
    extern __shared__ char dsm[];
    __shared__ int s_sp[SMAXK];
    const int sg = blockIdx.y;
    const int s = sg >> 3, g = sg & 7;
    const int s0 = g_cu[s];
    const int L = g_cu[s + 1] - s0;
    const int mBase = blockIdx.x * 64;
    if (mBase >= 4 * L) return;
    const int salst = g_salst[s];

    const int tid = threadIdx.x, wid = tid >> 5, lane = tid & 31;
    const int wm = wid >> 2, wn = wid & 3;
    const uint32_t sb = smem_to_u32(dsm);

    for (int j = tid; j < L; j += 256) {
        int sp = g_salpos[s0 + j];
        s_sp[j] = sp >= 0 ? sp - salst : -1;
    }

    // A tile: 64 rows, hi/lo (cp.async; bundled into first commit)
#pragma unroll
    for (int it = 0; it < 4; it++) {
        int idx = tid + it * 256;
        int r = idx >> 4, ch = idx & 15;
        uint32_t d = (uint32_t)(r * 256) + (((uint32_t)(ch ^ (r & 7))) << 4);
        int mm = mBase + r, il = mm >> 2, hh = mm & 3;
        bool v = il < L;
        size_t o = v ? (((size_t)(s0 + il) * NH + 4 * g + hh) * HD + ch * 8) : 0;
        cpa16(sb + d, g_qhi + o, v);
        cpa16(sb + A_LO + d, g_qlo + o, v);
    }

    // per-row metadata
    size_t id0[2], id1[2];
    ll pb0[2], pb1[2];
    bool ok0[2], ok1[2];
#pragma unroll
    for (int mf = 0; mf < 2; mf++) {
        int mr0 = mBase + wm * 32 + mf * 16 + (lane >> 2);
        int mr1 = mr0 + 8;
        int il0 = mr0 >> 2, h0 = mr0 & 3;
        int il1 = mr1 >> 2, h1 = mr1 & 3;
        ok0[mf] = il0 < L; ok1[mf] = il1 < L;
        id0[mf] = ok0[mf] ? ((size_t)(s0 + il0) * NH + 4 * g + h0) : 0;
        id1[mf] = ok1[mf] ? ((size_t)(s0 + il1) * NH + 4 * g + h1) : 0;
        int sp0 = ok0[mf] ? g_salpos[s0 + il0] : -1;
        int sp1 = ok1[mf] ? g_salpos[s0 + il1] : -1;
        pb0[mf] = sp0 >= 0 ? ((ll)sp0 * NH + 4 * g + h0) * SMAXK : -1;
        pb1[mf] = sp1 >= 0 ? ((ll)sp1 * NH + 4 * g + h1) * SMAXK : -1;
    }

    // prime: B tile 0 (A loads ride along in this commit group)
    qk_loadB(sb, tid, 0, s0, L, g);
    CP_COMMIT();

    float rs0[2] = {0.f, 0.f}, rs1[2] = {0.f, 0.f};

    for (int nt = 0; nt < 4; nt++) {
        CP_WAIT0();
        __syncthreads();

        float acc[2][4][4];
#pragma unroll
        for (int a = 0; a < 2; a++)
#pragma unroll
            for (int b = 0; b < 4; b++)
#pragma unroll
                for (int c = 0; c < 4; c++) acc[a][b][c] = 0.f;

        hmma_tile64(sb, acc, wid, lane);
        __syncthreads();
        // B buffer is dead after the MMA: issue next tile's loads NOW,
        // let the epilogue below hide their latency (single buffer, zero extra smem)
        if (nt < 3) {
            qk_loadB(sb, tid, nt + 1, s0, L, g);
            CP_COMMIT();
        }

#pragma unroll
        for (int nf = 0; nf < 4; nf++) {
            int col = nt * 128 + wn * 32 + nf * 8 + (lane & 3) * 2;
            bool c0 = col < L, c1 = col + 1 < L;
            int spa = c0 ? s_sp[col] : -1;
            int spb = c1 ? s_sp[col + 1] : -1;
#pragma unroll
            for (int mf = 0; mf < 2; mf++) {
                float* c = acc[mf][nf];
                float e0 = (ok0[mf] && c0) ? fexp2(c[0] * SCALE_L2E) : 0.f;
                float e1 = (ok0[mf] && c1) ? fexp2(c[1] * SCALE_L2E) : 0.f;
                float e2 = (ok1[mf] && c0) ? fexp2(c[2] * SCALE_L2E) : 0.f;
                float e3 = (ok1[mf] && c1) ? fexp2(c[3] * SCALE_L2E) : 0.f;
                rs0[mf] += e0 + e1;
                rs1[mf] += e2 + e3;

                if (spa >= 0) {
                    if (ok0[mf]) { __nv_bfloat16 h, l; bf_split(e0, h, l);
                        g_Psal_hi[id0[mf] * 128 + spa] = h; g_Psal_lo[id0[mf] * 128 + spa] = l; }
                    if (ok1[mf]) { __nv_bfloat16 h, l; bf_split(e2, h, l);
                        g_Psal_hi[id1[mf] * 128 + spa] = h; g_Psal_lo[id1[mf] * 128 + spa] = l; }
                }
                if (spb >= 0) {
                    if (ok0[mf]) { __nv_bfloat16 h, l; bf_split(e1, h, l);
                        g_Psal_hi[id0[mf] * 128 + spb] = h; g_Psal_lo[id0[mf] * 128 + spb] = l; }
                    if (ok1[mf]) { __nv_bfloat16 h, l; bf_split(e3, h, l);
                        g_Psal_hi[id1[mf] * 128 + spb] = h; g_Psal_lo[id1[mf] * 128 + spb] = l; }
                }
                if (pb0[mf] >= 0 && c0) {
                    __nv_bfloat16 h0, l0, h1, l1;
                    bf_split(e0, h0, l0); bf_split(e1, h1, l1);
                    __nv_bfloat162 ph; ph.x = h0; ph.y = h1;
                    __nv_bfloat162 pl; pl.x = l0; pl.y = l1;
                    *(__nv_bfloat162*)(g_Posal_hi + pb0[mf] + col) = ph;
                    *(__nv_bfloat162*)(g_Posal_lo + pb0[mf] + col) = pl;
                }
                if (pb1[mf] >= 0 && c0) {
                    __nv_bfloat16 h0, l0, h1, l1;
                    bf_split(e2, h0, l0); bf_split(e3, h1, l1);
                    __nv_bfloat162 ph; ph.x = h0; ph.y = h1;
                    __nv_bfloat162 pl; pl.x = l0; pl.y = l1;
                    *(__nv_bfloat162*)(g_Posal_hi + pb1[mf] + col) = ph;
                    *(__nv_bfloat162*)(g_Posal_lo + pb1[mf] + col) = pl;
                }
            }
        }
    }

    // final rowsum reduction -> g_inv (reuse A region)
#pragma unroll
    for (int mf = 0; mf < 2; mf++) {
        rs0[mf] += __shfl_xor_sync(0xffffffffu, rs0[mf], 1);
        rs0[mf] += __shfl_xor_sync(0xffffffffu, rs0[mf], 2);
        rs1[mf] += __shfl_xor_sync(0xffffffffu, rs1[mf], 1);
        rs1[mf] += __shfl_xor_sync(0xffffffffu, rs1[mf], 2);
    }
    __syncthreads();
    float* red = (float*)dsm;
    if ((lane & 3) == 0) {
#pragma unroll
        for (int mf = 0; mf < 2; mf++) {
            int r0 = wm * 32 + mf * 16 + (lane >> 2);
            red[r0 * 4 + wn] = rs0[mf];
            red[(r0 + 8) * 4 + wn] = rs1[mf];
        }
    }
    __syncthreads();
    if (tid < 64) {
        int mm = mBase + tid, il = mm >> 2, h = mm & 3;
        if (il < L) {
            float s4 = red[tid * 4] + red[tid * 4 + 1] + red[tid * 4 + 2] + red[tid * 4 + 3];
            g_inv[(size_t)(s0 + il) * NH + 4 * g + h] = 1.f / s4;
        }
    }
}

// ---------------- K2 (merged): osal (x<8) || delta (x>=8), 64-row tiles ----------------
__global__ void __launch_bounds__(256, 2) k_pv(const float* __restrict__ cc, float* __restrict__ outc) {
    extern __shared__ char dsm[];
    const int sg = blockIdx.y;
    const int s = sg >> 3, g = sg & 7;
    const int s0 = g_cu[s];
    const int L = g_cu[s + 1] - s0;
    const int salst = g_salst[s], salcnt = g_salcnt[s];

    const int tid = threadIdx.x, wid = tid >> 5, lane = tid & 31;
    const int wm = wid >> 2, wn = wid & 3;
    const uint32_t sb = smem_to_u32(dsm);

    float acc[2][4][4];
#pragma unroll
    for (int a = 0; a < 2; a++)
#pragma unroll
        for (int b = 0; b < 4; b++)
#pragma unroll
            for (int c = 0; c < 4; c++) acc[a][b][c] = 0.f;

    if (blockIdx.x < 8) {
        const int mBase = blockIdx.x * 64;
        if (mBase >= 4 * salcnt) return;

        for (int kc = 0; kc * 128 < L; kc++) {
#pragma unroll
            for (int it = 0; it < 4; it++) {
                int idx = tid + it * 256;
                int r = idx >> 4, ch = idx & 15;
                uint32_t d = (uint32_t)(r * 256) + (((uint32_t)(ch ^ (r & 7))) << 4);
                int m = mBase + r, saloc = m >> 2, hh = m & 3;
                int kk = kc * 128 + ch * 8;
                bool va = (saloc < salcnt) && (kk < L);
                size_t ia = va ? (((size_t)(salst + saloc) * NH + 4 * g + hh) * SMAXK + kk) : 0;
                cpa16(sb + d, g_Posal_hi + ia, va);
                cpa16(sb + A_LO + d, g_Posal_lo + ia, va);
            }
#pragma unroll
            for (int it = 0; it < 8; it++) {
                int idx = tid + it * 256;
                int r = idx >> 4, ch = idx & 15;
                uint32_t d = (uint32_t)(r * 256) + (((uint32_t)(ch ^ (r & 7))) << 4);
                int kk = kc * 128 + ch * 8;
                bool vb = (kk < L);
                size_t ib = vb ? (((size_t)(g * HD + r)) * TT + s0 + kk) : 0;
                cpa16(sb + B_HI + d, g_vnT_hi + ib, vb);
                cpa16(sb + B_HI + B_LO + d, g_vnT_lo + ib, vb);
            }
            CP_COMMIT();
            CP_WAIT0();
            __syncthreads();
            hmma_tile64(sb, acc, wid, lane);
            __syncthreads();
        }

#pragma unroll
        for (int mf = 0; mf < 2; mf++) {
            int mr0 = mBase + wm * 32 + mf * 16 + (lane >> 2);
            int mr1 = mr0 + 8;
            int sa0 = mr0 >> 2, h0 = mr0 & 3;
            int sa1 = mr1 >> 2, h1 = mr1 & 3;
            bool ok0 = sa0 < salcnt, ok1 = sa1 < salcnt;
            size_t id0 = 0, id1 = 0;
            float inv0 = 0.f, inv1 = 0.f;
            if (ok0) { id0 = (size_t)g_idx[salst + sa0] * NH + 4 * g + h0; inv0 = g_inv[id0]; }
            if (ok1) { id1 = (size_t)g_idx[salst + sa1] * NH + 4 * g + h1; inv1 = g_inv[id1]; }
#pragma unroll
            for (int nf = 0; nf < 4; nf++) {
                int dcol = wn * 32 + nf * 8 + (lane & 3) * 2;
                float* c = acc[mf][nf];
                if (ok0) *(float2*)(outc + id0 * HD + dcol) = make_float2(inv0 * c[0], inv0 * c[1]);
                if (ok1) *(float2*)(outc + id1 * HD + dcol) = make_float2(inv1 * c[2], inv1 * c[3]);
            }
        }
    } else {
        const int mBase = (blockIdx.x - 8) * 64;
        if (mBase >= 4 * L) return;

#pragma unroll
        for (int it = 0; it < 4; it++) {
            int idx = tid + it * 256;
            int r = idx >> 4, ch = idx & 15;
            uint32_t d = (uint32_t)(r * 256) + (((uint32_t)(ch ^ (r & 7))) << 4);
            int mm = mBase + r, il = mm >> 2, hh = mm & 3;
            bool va = (il < L) && (ch * 8 < salcnt);
            size_t ia = va ? (((size_t)(s0 + il) * NH + 4 * g + hh) * 128 + ch * 8) : 0;
            cpa16(sb + d, g_Psal_hi + ia, va);
            cpa16(sb + A_LO + d, g_Psal_lo + ia, va);
        }
#pragma unroll
        for (int it = 0; it < 8; it++) {
            int idx = tid + it * 256;
            int r = idx >> 4, ch = idx & 15;
            uint32_t d = (uint32_t)(r * 256) + (((uint32_t)(ch ^ (r & 7))) << 4);
            bool vb = (ch * 8 < salcnt);
            size_t ib = vb ? (((size_t)(g * HD + r)) * NSALT + salst + ch * 8) : 0;
            cpa16(sb + B_HI + d, g_vdT_hi + ib, vb);
            cpa16(sb + B_HI + B_LO + d, g_vdT_lo + ib, vb);
        }
        CP_COMMIT();
        CP_WAIT0();
        __syncthreads();
        hmma_tile64(sb, acc, wid, lane);

#pragma unroll
        for (int mf = 0; mf < 2; mf++) {
            int mr0 = mBase + wm * 32 + mf * 16 + (lane >> 2);
            int mr1 = mr0 + 8;
            int il0 = mr0 >> 2, h0 = mr0 & 3;
            int il1 = mr1 >> 2, h1 = mr1 & 3;
            bool ok0 = (il0 < L) && (g_salpos[s0 + il0] < 0);
            bool ok1 = (il1 < L) && (g_salpos[s0 + il1] < 0);
            size_t id0 = (size_t)(s0 + il0) * NH + 4 * g + h0;
            size_t id1 = (size_t)(s0 + il1) * NH + 4 * g + h1;
            float inv0 = ok0 ? g_inv[id0] : 0.f;
            float inv1 = ok1 ? g_inv[id1] : 0.f;
#pragma unroll
            for (int nf = 0; nf < 4; nf++) {
                int dcol = wn * 32 + nf * 8 + (lane & 3) * 2;
                float* c = acc[mf][nf];
                if (ok0) {
                    size_t ob = id0 * HD + dcol;
                    float2 cv = *(const float2*)(cc + ob);
                    *(float2*)(outc + ob) = make_float2(cv.x + inv0 * c[0], cv.y + inv0 * c[1]);
                }
                if (ok1) {
                    size_t ob = id1 * HD + dcol;
                    float2 cv = *(const float2*)(cc + ob);
                    *(float2*)(outc + ob) = make_float2(cv.x + inv1 * c[2], cv.y + inv1 * c[3]);
                }
            }
        }
    }
}

// ---------------- K3: per-row cosine similarity (warp-shuffle reduction) ----------------
__global__ void __launch_bounds__(512) k_cos(const float* __restrict__ cc, const float* __restrict__ outc,
                                             float* __restrict__ cosv) {
    const int tid = threadIdx.x, wid = tid >> 5, lane = tid & 31;
    size_t base = (size_t)blockIdx.x * (NH * HD);
    const float4* a4 = (const float4*)(cc + base);
    const float4* b4 = (const float4*)(outc + base);
    float ab = 0.f, aa = 0.f, bb = 0.f;
#pragma unroll
    for (int j = 0; j < 2; j++) {
        float4 x = a4[tid + j * 512], y = b4[tid + j * 512];
        ab += x.x * y.x + x.y * y.y + x.z * y.z + x.w * y.w;
        aa += x.x * x.x + x.y * x.y + x.z * x.z + x.w * x.w;
        bb += y.x * y.x + y.y * y.y + y.z * y.z + y.w * y.w;
    }
#pragma unroll
    for (int o = 16; o; o >>= 1) {
        ab += __shfl_xor_sync(0xffffffffu, ab, o);
        aa += __shfl_xor_sync(0xffffffffu, aa, o);
        bb += __shfl_xor_sync(0xffffffffu, bb, o);
    }
    __shared__ float sh[3][16];
    if (lane == 0) { sh[0][wid] = ab; sh[1][wid] = aa; sh[2][wid] = bb; }
    __syncthreads();
    if (tid < 32) {
        float a2 = (tid < 16) ? sh[0][tid] : 0.f;
        float b2 = (tid < 16) ? sh[1][tid] : 0.f;
        float c2 = (tid < 16) ? sh[2][tid] : 0.f;
#pragma unroll
        for (int o = 8; o; o >>= 1) {
            a2 += __shfl_xor_sync(0xffffffffu, a2, o);
            b2 += __shfl_xor_sync(0xffffffffu, b2, o);
            c2 += __shfl_xor_sync(0xffffffffu, c2, o);
        }
        if (tid == 0)
            cosv[blockIdx.x] = a2 / (sqrtf(b2) * sqrtf(c2) + 1e-8f);
    }
}

// ---------------- launch ----------------
extern "C" void kernel_launch(void* const* d_in, const int* in_sizes, int n_in,
                              void* d_out, int out_size) {
    const float* q       = (const float*)d_in[0];
    const float* k       = (const float*)d_in[1];
    const float* v       = (const float*)d_in[2];
    const float* v_cache = (const float*)d_in[3];
    const float* c_cache = (const float*)d_in[4];
    const void*  idx     = d_in[5];
    const void*  cu      = d_in[6];

    float* outc = (float*)d_out;
    float* cosv = outc + (size_t)(out_size - TT);

    cudaFuncSetAttribute(k_qk,  cudaFuncAttributeMaxDynamicSharedMemorySize, 98304);
    cudaFuncSetAttribute(k_pv,  cudaFuncAttributeMaxDynamicSharedMemorySize, 98304);
    cudaFuncSetAttribute(k_pre, cudaFuncAttributeMaxDynamicSharedMemorySize, 16512);

    k_prep<<<1, 256>>>(idx, cu);
    k_pre<<<CVT_BLKS + VN_BLKS + VD_BLKS, 256, 16512>>>(q, k, v, v_cache);
    k_qk<<<dim3(32, 32), 256, 98304>>>();
    k_pv<<<dim3(40, 32), 256, 98304>>>(c_cache, outc);
    k_cos<<<TT, 512>>>(c_cache, outc, cosv);
}

// round 10
// speedup vs baseline: 1.1187x; 1.0706x over previous
#include <cuda_runtime.h>
#include <cuda_bf16.h>
#include <math.h>
#include <stdint.h>

typedef unsigned long long ull;
typedef long long ll;

#define TT    2048
#define NH    32
#define NKV   8
#define HD    128
#define NSALT 512
#define NSEG  4
#define SMAXK 512
#define SCALE_L2E 0.12751742788f   /* (1/sqrt(128)) * log2(e) */

#define CVT_BLKS 10240
#define VN_BLKS  512
#define VD_BLKS  128

// k_qk smem (96KB): Q_hi[0,16K) Q_lo[16K,32K) K_hi[32K,48K) K_lo[48K,64K) Pst_hi[64K,80K) Pst_lo[80K,96K)
// PV phase reuses: vdT_hi -> [0,32K), vdT_lo -> [32K,64K)
#define KOFF 32768u
#define PST  65536u
// k_pv smem (96KB): A_hi[0,16K) A_lo[16K,32K) B_hi[32K,64K) B_lo[64K,96K)
#define A_LO 16384u
#define B_HI 32768u

// ---------------- scratch (device globals: allocation-free) ----------------
__device__ float g_inv[(size_t)TT * NH];
__device__ __nv_bfloat16 g_qhi[(size_t)TT * NH * HD];
__device__ __nv_bfloat16 g_qlo[(size_t)TT * NH * HD];
__device__ __nv_bfloat16 g_khi[(size_t)TT * NKV * HD];
__device__ __nv_bfloat16 g_klo[(size_t)TT * NKV * HD];
__device__ __nv_bfloat16 g_Posal_hi[(size_t)NSALT * NH * SMAXK];
__device__ __nv_bfloat16 g_Posal_lo[(size_t)NSALT * NH * SMAXK];
__device__ __nv_bfloat16 g_vnT_hi[(size_t)NKV * HD * TT];
__device__ __nv_bfloat16 g_vnT_lo[(size_t)NKV * HD * TT];
__device__ __nv_bfloat16 g_vdT_hi[(size_t)NKV * HD * NSALT];
__device__ __nv_bfloat16 g_vdT_lo[(size_t)NKV * HD * NSALT];
__device__ int   g_idx[NSALT];
__device__ int   g_cu[NSEG + 1];
__device__ int   g_salpos[TT];
__device__ int   g_salst[NSEG];
__device__ int   g_salcnt[NSEG];

// ---------------- helpers ----------------
__device__ __forceinline__ uint32_t smem_to_u32(const void* p) {
    uint32_t a;
    asm("{ .reg .u64 t; cvta.to.shared.u64 t, %1; cvt.u32.u64 %0, t; }" : "=r"(a) : "l"(p));
    return a;
}
__device__ __forceinline__ void ldsm4(uint32_t* r, uint32_t addr) {
    asm volatile("ldmatrix.sync.aligned.m8n8.x4.shared.b16 {%0,%1,%2,%3}, [%4];"
        : "=r"(r[0]), "=r"(r[1]), "=r"(r[2]), "=r"(r[3]) : "r"(addr));
}
__device__ __forceinline__ void mma16816(float* c, const uint32_t* a, uint32_t b0, uint32_t b1) {
    asm volatile("mma.sync.aligned.m16n8k16.row.col.f32.bf16.bf16.f32 "
        "{%0,%1,%2,%3}, {%4,%5,%6,%7}, {%8,%9}, {%0,%1,%2,%3};"
        : "+f"(c[0]), "+f"(c[1]), "+f"(c[2]), "+f"(c[3])
        : "r"(a[0]), "r"(a[1]), "r"(a[2]), "r"(a[3]), "r"(b0), "r"(b1));
}
__device__ __forceinline__ void cpa16(uint32_t dst, const void* src, bool valid) {
    int sz = valid ? 16 : 0;
    asm volatile("cp.async.cg.shared.global [%0], [%1], 16, %2;"
        :: "r"(dst), "l"(src), "r"(sz) : "memory");
}
#define CP_COMMIT() asm volatile("cp.async.commit_group;" ::: "memory")
#define CP_WAIT0()  asm volatile("cp.async.wait_group 0;" ::: "memory")

__device__ __forceinline__ float fexp2(float x) {
    float r;
    asm("ex2.approx.f32 %0, %1;" : "=f"(r) : "f"(x));
    return r;
}
__device__ __forceinline__ void bf_split(float x, __nv_bfloat16& h, __nv_bfloat16& l) {
    h = __float2bfloat16(x);
    l = __float2bfloat16(x - __bfloat162float(h));
}

// 64(m)x128(n)x128(k) 3-pass HMMA: A hi@aOff, lo@aOff+16K; B hi@bOff, lo@bOff+32K.
// Rows 256B, 16B-chunk XOR swizzle. 8 warps = 2(m) x 4(n). (Verified rounds 4-9.)
__device__ __forceinline__ void hmma_AB(uint32_t sb, uint32_t aOff, uint32_t bOff,
                                        float acc[2][4][4], int wid, int lane) {
    const int wm = wid >> 2, wn = wid & 3;
    uint32_t a_ad[2], a_rx[2];
#pragma unroll
    for (int mf = 0; mf < 2; mf++) {
        int row = wm * 32 + mf * 16 + (lane & 15);
        a_ad[mf] = sb + aOff + row * 256;
        a_rx[mf] = ((uint32_t)(row & 7)) << 4;
    }
    const int achunk = (lane >> 4);
    uint32_t b_ad[2], b_rx[2];
#pragma unroll
    for (int bg = 0; bg < 2; bg++) {
        int n = wn * 32 + bg * 16 + (lane & 7) + ((lane >> 4) << 3);
        b_ad[bg] = sb + bOff + n * 256;
        b_rx[bg] = ((uint32_t)(n & 7)) << 4;
    }
    const int bchunk = (lane >> 3) & 1;
#pragma unroll
    for (int ks = 0; ks < 8; ks++) {
        uint32_t ah[2][4], al[2][4];
#pragma unroll
        for (int mf = 0; mf < 2; mf++) {
            uint32_t coff = (((uint32_t)(ks * 2 + achunk)) << 4) ^ a_rx[mf];
            ldsm4(ah[mf], a_ad[mf] + coff);
            ldsm4(al[mf], a_ad[mf] + 16384u + coff);
        }
        uint32_t bh[2][4], bl[2][4];
#pragma unroll
        for (int bg = 0; bg < 2; bg++) {
            uint32_t coff = (((uint32_t)(ks * 2 + bchunk)) << 4) ^ b_rx[bg];
            ldsm4(bh[bg], b_ad[bg] + coff);
            ldsm4(bl[bg], b_ad[bg] + 32768u + coff);
        }
#pragma unroll
        for (int mf = 0; mf < 2; mf++)
#pragma unroll
            for (int nf = 0; nf < 4; nf++) {
                int bg = nf >> 1, sel = (nf & 1) * 2;
                mma16816(acc[mf][nf], ah[mf], bh[bg][sel], bh[bg][sel + 1]);
                mma16816(acc[mf][nf], ah[mf], bl[bg][sel], bl[bg][sel + 1]);
                mma16816(acc[mf][nf], al[mf], bh[bg][sel], bh[bg][sel + 1]);
            }
    }
}

// 64(m)x64(n)x128(k) 3-pass HMMA (QK phase). A hi@0, lo@16K; B hi@KOFF, lo@KOFF+16K.
// (Verified round 8.)
__device__ __forceinline__ void hmma_64(uint32_t sb, float acc[2][2][4], int wid, int lane) {
    const int wm = wid >> 2, wn = wid & 3;
    uint32_t a_ad[2], a_rx[2];
#pragma unroll
    for (int mf = 0; mf < 2; mf++) {
        int row = wm * 32 + mf * 16 + (lane & 15);
        a_ad[mf] = sb + row * 256;
        a_rx[mf] = ((uint32_t)(row & 7)) << 4;
    }
    const int achunk = (lane >> 4);
    int n = wn * 16 + (lane & 7) + ((lane >> 4) << 3);
    uint32_t b_ad = sb + KOFF + n * 256;
    uint32_t b_rx = ((uint32_t)(n & 7)) << 4;
    const int bchunk = (lane >> 3) & 1;
#pragma unroll
    for (int ks = 0; ks < 8; ks++) {
        uint32_t ah[2][4], al[2][4];
#pragma unroll
        for (int mf = 0; mf < 2; mf++) {
            uint32_t coff = (((uint32_t)(ks * 2 + achunk)) << 4) ^ a_rx[mf];
            ldsm4(ah[mf], a_ad[mf] + coff);
            ldsm4(al[mf], a_ad[mf] + 16384u + coff);
        }
        uint32_t bh[4], bl[4];
        {
            uint32_t coff = (((uint32_t)(ks * 2 + bchunk)) << 4) ^ b_rx;
            ldsm4(bh, b_ad + coff);
            ldsm4(bl, b_ad + 16384u + coff);
        }
#pragma unroll
        for (int mf = 0; mf < 2; mf++)
#pragma unroll
            for (int nf = 0; nf < 2; nf++) {
                int sel = nf * 2;
                mma16816(acc[mf][nf], ah[mf], bh[sel], bh[sel + 1]);
                mma16816(acc[mf][nf], ah[mf], bl[sel], bl[sel + 1]);
                mma16816(acc[mf][nf], al[mf], bh[sel], bh[sel + 1]);
            }
    }
}

// store one P value (hi+lo planes) into swizzled Pstage
__device__ __forceinline__ void sts_p(char* dsm, int row, int salcol, float val) {
    __nv_bfloat16 h, l;
    bf_split(val, h, l);
    uint32_t off = (uint32_t)row * 256 + ((((uint32_t)(salcol >> 3)) ^ (uint32_t)(row & 7)) << 4)
                 + (uint32_t)((2 * salcol) & 15);
    *(__nv_bfloat16*)(dsm + PST + off) = h;
    *(__nv_bfloat16*)(dsm + PST + 16384u + off) = l;
}

// ---------------- K0a: decode indices, segment tables ----------------
__global__ void k_prep(const void* idx_raw, const void* cu_raw) {
    const int* i32 = (const int*)idx_raw;
    const int* c32 = (const int*)cu_raw;
    const bool idx64 = (i32[1] == 0);
    const bool cu64  = (c32[1] == 0);
    const int t = threadIdx.x;

    for (int i = t; i < NSALT; i += 256)
        g_idx[i] = idx64 ? (int)((const long long*)idx_raw)[i] : i32[i];
    if (t <= NSEG)
        g_cu[t] = cu64 ? (int)((const long long*)cu_raw)[t] : c32[t];
    for (int i = t; i < TT; i += 256) g_salpos[i] = -1;
    __syncthreads();
    for (int i = t; i < NSALT; i += 256) g_salpos[g_idx[i]] = i;
    if (t == 0) {
        for (int s = 0; s < NSEG; s++) {
            int a = 0;
            while (a < NSALT && g_idx[a] < g_cu[s]) a++;
            int b = a;
            while (b < NSALT && g_idx[b] < g_cu[s + 1]) b++;
            g_salst[s] = a;
            g_salcnt[s] = b - a;
        }
    }
}

// ---------------- K0b (merged): cvt || build_vn || build_vd ----------------
__global__ void __launch_bounds__(256) k_pre(const float* __restrict__ q, const float* __restrict__ kk,
                                             const float* __restrict__ v, const float* __restrict__ vc) {
    extern __shared__ float tile[];   // [32][129]
    const int bx = blockIdx.x;
    const int tid = threadIdx.x;

    if (bx < CVT_BLKS) {
        const int nq4 = TT * NH * HD / 4;
        int i = bx * 256 + tid;
        float4 x;
        __nv_bfloat162 *h2, *l2;
        if (i < nq4) {
            x = ((const float4*)q)[i];
            h2 = (__nv_bfloat162*)g_qhi + 2 * (size_t)i;
            l2 = (__nv_bfloat162*)g_qlo + 2 * (size_t)i;
        } else {
            int j = i - nq4;
            x = ((const float4*)kk)[j];
            h2 = (__nv_bfloat162*)g_khi + 2 * (size_t)j;
            l2 = (__nv_bfloat162*)g_klo + 2 * (size_t)j;
        }
        __nv_bfloat162 a = __float22bfloat162_rn(make_float2(x.x, x.y));
        __nv_bfloat162 b = __float22bfloat162_rn(make_float2(x.z, x.w));
        __nv_bfloat162 al = __float22bfloat162_rn(make_float2(x.x - __low2float(a), x.y - __high2float(a)));
        __nv_bfloat162 bl = __float22bfloat162_rn(make_float2(x.z - __low2float(b), x.w - __high2float(b)));
        h2[0] = a; h2[1] = b; l2[0] = al; l2[1] = bl;
        return;
    }

    if (bx < CVT_BLKS + VN_BLKS) {
        int t2 = bx - CVT_BLKS;
        int kc = t2 >> 3, g = t2 & 7;
#pragma unroll
        for (int it = 0; it < 4; it++) {
            int fi = tid + it * 256;
            int key = fi >> 5, c4 = fi & 31;
            int gk = kc * 32 + key;
            int sp = g_salpos[gk];
            const float* src = (sp >= 0) ? v + ((size_t)sp * NKV + g) * HD + c4 * 4
                                         : vc + ((size_t)gk * NKV + g) * HD + c4 * 4;
            float4 x = *(const float4*)src;
            float* tr = tile + key * 129 + c4 * 4;
            tr[0] = x.x; tr[1] = x.y; tr[2] = x.z; tr[3] = x.w;
        }
        __syncthreads();
#pragma unroll
        for (int it = 0; it < 8; it++) {
            int wi = tid + it * 256;
            int d = wi >> 4, kp = wi & 15;
            float v0 = tile[(2 * kp) * 129 + d], v1 = tile[(2 * kp + 1) * 129 + d];
            __nv_bfloat16 h0, l0, h1, l1;
            bf_split(v0, h0, l0); bf_split(v1, h1, l1);
            __nv_bfloat162 ph; ph.x = h0; ph.y = h1;
            __nv_bfloat162 pl; pl.x = l0; pl.y = l1;
            size_t dst = ((size_t)g * HD + d) * TT + kc * 32 + 2 * kp;
            *(__nv_bfloat162*)(g_vnT_hi + dst) = ph;
            *(__nv_bfloat162*)(g_vnT_lo + dst) = pl;
        }
        return;
    }

    {
        int t2 = bx - CVT_BLKS - VN_BLKS;
        int kc = t2 >> 3, g = t2 & 7;
#pragma unroll
        for (int it = 0; it < 4; it++) {
            int fi = tid + it * 256;
            int sidx = fi >> 5, c4 = fi & 31;
            int sal = kc * 32 + sidx;
            const float* pv = v  + ((size_t)sal * NKV + g) * HD + c4 * 4;
            const float* pc = vc + ((size_t)g_idx[sal] * NKV + g) * HD + c4 * 4;
            float4 a = *(const float4*)pv;
            float4 b = *(const float4*)pc;
            float* tr = tile + sidx * 129 + c4 * 4;
            tr[0] = a.x - b.x; tr[1] = a.y - b.y; tr[2] = a.z - b.z; tr[3] = a.w - b.w;
        }
        __syncthreads();
#pragma unroll
        for (int it = 0; it < 8; it++) {
            int wi = tid + it * 256;
            int d = wi >> 4, kp = wi & 15;
            float v0 = tile[(2 * kp) * 129 + d], v1 = tile[(2 * kp + 1) * 129 + d];
            __nv_bfloat16 h0, l0, h1, l1;
            bf_split(v0, h0, l0); bf_split(v1, h1, l1);
            __nv_bfloat162 ph; ph.x = h0; ph.y = h1;
            __nv_bfloat162 pl; pl.x = l0; pl.y = l1;
            size_t dst = ((size_t)g * HD + d) * NSALT + kc * 32 + 2 * kp;
            *(__nv_bfloat162*)(g_vdT_hi + dst) = ph;
            *(__nv_bfloat162*)(g_vdT_lo + dst) = pl;
        }
    }
}

// ---------------- K1: fused QK^T + exp + rowsum + delta-PV ----------------
__device__ __forceinline__ void qk_loadK(uint32_t sb, int tid, int nt, int s0, int L, int g) {
#pragma unroll
    for (int it = 0; it < 4; it++) {
        int idx = tid + it * 256;
        int r = idx >> 4, ch = idx & 15;
        uint32_t d = (uint32_t)(r * 256) + (((uint32_t)(ch ^ (r & 7))) << 4);
        int jg = nt * 64 + r;
        bool v = jg < L;
        size_t o = v ? (((size_t)(s0 + jg) * NKV + g) * HD + ch * 8) : 0;
        cpa16(sb + KOFF + d, g_khi + o, v);
        cpa16(sb + KOFF + 16384u + d, g_klo + o, v);
    }
}

__global__ void __launch_bounds__(256, 2) k_qk(const float* __restrict__ cc, float* __restrict__ outc) {
    extern __shared__ char dsm[];
    __shared__ int s_sp[SMAXK];
    __shared__ float s_red[64 * 4];
    const int sg = blockIdx.y;
    const int s = sg >> 3, g = sg & 7;
    const int s0 = g_cu[s];
    const int L = g_cu[s + 1] - s0;
    const int mBase = blockIdx.x * 64;
    if (mBase >= 4 * L) return;
    const int salst = g_salst[s], salcnt = g_salcnt[s];

    const int tid = threadIdx.x, wid = tid >> 5, lane = tid & 31;
    const int wm = wid >> 2, wn = wid & 3;
    const uint32_t sb = smem_to_u32(dsm);

    for (int j = tid; j < L; j += 256) {
        int sp = g_salpos[s0 + j];
        s_sp[j] = sp >= 0 ? sp - salst : -1;
    }

    // zero Pstage (32KB)
    {
        uint4 z = make_uint4(0, 0, 0, 0);
#pragma unroll
        for (int it = 0; it < 8; it++)
            *(uint4*)(dsm + PST + (size_t)(tid + it * 256) * 16) = z;
    }

    // A tile (Q, 64 rows hi/lo) + K tile 0
#pragma unroll
    for (int it = 0; it < 4; it++) {
        int idx = tid + it * 256;
        int r = idx >> 4, ch = idx & 15;
        uint32_t d = (uint32_t)(r * 256) + (((uint32_t)(ch ^ (r & 7))) << 4);
        int mm = mBase + r, il = mm >> 2, hh = mm & 3;
        bool v = il < L;
        size_t o = v ? (((size_t)(s0 + il) * NH + 4 * g + hh) * HD + ch * 8) : 0;
        cpa16(sb + d, g_qhi + o, v);
        cpa16(sb + 16384u + d, g_qlo + o, v);
    }
    qk_loadK(sb, tid, 0, s0, L, g);
    CP_COMMIT();

    // per-row metadata (Posal base for salient rows)
    ll pb0[2], pb1[2];
    bool ok0[2], ok1[2];
    int rb[2];
#pragma unroll
    for (int mf = 0; mf < 2; mf++) {
        rb[mf] = wm * 32 + mf * 16 + (lane >> 2);
        int mr0 = mBase + rb[mf];
        int mr1 = mr0 + 8;
        int il0 = mr0 >> 2, h0 = mr0 & 3;
        int il1 = mr1 >> 2, h1 = mr1 & 3;
        ok0[mf] = il0 < L; ok1[mf] = il1 < L;
        int sp0 = ok0[mf] ? g_salpos[s0 + il0] : -1;
        int sp1 = ok1[mf] ? g_salpos[s0 + il1] : -1;
        pb0[mf] = sp0 >= 0 ? ((ll)sp0 * NH + 4 * g + h0) * SMAXK : -1;
        pb1[mf] = sp1 >= 0 ? ((ll)sp1 * NH + 4 * g + h1) * SMAXK : -1;
    }

    float rs0[2] = {0.f, 0.f}, rs1[2] = {0.f, 0.f};

    for (int nt = 0; nt < 8; nt++) {
        CP_WAIT0();
        __syncthreads();

        float acc[2][2][4];
#pragma unroll
        for (int a = 0; a < 2; a++)
#pragma unroll
            for (int b = 0; b < 2; b++)
#pragma unroll
                for (int c = 0; c < 4; c++) acc[a][b][c] = 0.f;

        hmma_64(sb, acc, wid, lane);
        __syncthreads();   // K (and on last tile, Q) now dead
        if (nt < 7) {
            qk_loadK(sb, tid, nt + 1, s0, L, g);
            CP_COMMIT();
        } else {
            // vdT tile: hi -> [0,32K), lo -> [32K,64K): [128 d][128 sal]
#pragma unroll
            for (int it = 0; it < 8; it++) {
                int idx = tid + it * 256;
                int r = idx >> 4, ch = idx & 15;
                uint32_t d = (uint32_t)(r * 256) + (((uint32_t)(ch ^ (r & 7))) << 4);
                bool vb = (ch * 8 < salcnt);
                size_t ib = vb ? (((size_t)(g * HD + r)) * NSALT + salst + ch * 8) : 0;
                cpa16(sb + d, g_vdT_hi + ib, vb);
                cpa16(sb + 32768u + d, g_vdT_lo + ib, vb);
            }
            CP_COMMIT();
        }

        // epilogue: exp, rowsum, Pstage STS (salient cols), Posal STG (salient rows)
#pragma unroll
        for (int nf = 0; nf < 2; nf++) {
            int col = nt * 64 + wn * 16 + nf * 8 + (lane & 3) * 2;
            bool c0 = col < L, c1 = col + 1 < L;
            int spa = c0 ? s_sp[col] : -1;
            int spb = c1 ? s_sp[col + 1] : -1;
#pragma unroll
            for (int mf = 0; mf < 2; mf++) {
                float* c = acc[mf][nf];
                float e0 = (ok0[mf] && c0) ? fexp2(c[0] * SCALE_L2E) : 0.f;
                float e1 = (ok0[mf] && c1) ? fexp2(c[1] * SCALE_L2E) : 0.f;
                float e2 = (ok1[mf] && c0) ? fexp2(c[2] * SCALE_L2E) : 0.f;
                float e3 = (ok1[mf] && c1) ? fexp2(c[3] * SCALE_L2E) : 0.f;
                rs0[mf] += e0 + e1;
                rs1[mf] += e2 + e3;
                int r0 = rb[mf], r1 = r0 + 8;
                if (spa >= 0) {
                    if (ok0[mf]) sts_p(dsm, r0, spa, e0);
                    if (ok1[mf]) sts_p(dsm, r1, spa, e2);
                }
                if (spb >= 0) {
                    if (ok0[mf]) sts_p(dsm, r0, spb, e1);
                    if (ok1[mf]) sts_p(dsm, r1, spb, e3);
                }
                if (pb0[mf] >= 0 && c0) {
                    __nv_bfloat16 h0, l0, h1, l1;
                    bf_split(e0, h0, l0); bf_split(e1, h1, l1);
                    __nv_bfloat162 ph; ph.x = h0; ph.y = h1;
                    __nv_bfloat162 pl; pl.x = l0; pl.y = l1;
                    *(__nv_bfloat162*)(g_Posal_hi + pb0[mf] + col) = ph;
                    *(__nv_bfloat162*)(g_Posal_lo + pb0[mf] + col) = pl;
                }
                if (pb1[mf] >= 0 && c0) {
                    __nv_bfloat16 h0, l0, h1, l1;
                    bf_split(e2, h0, l0); bf_split(e3, h1, l1);
                    __nv_bfloat162 ph; ph.x = h0; ph.y = h1;
                    __nv_bfloat162 pl; pl.x = l0; pl.y = l1;
                    *(__nv_bfloat162*)(g_Posal_hi + pb1[mf] + col) = ph;
                    *(__nv_bfloat162*)(g_Posal_lo + pb1[mf] + col) = pl;
                }
            }
        }
    }

    // rowsum reduction across n-warps
#pragma unroll
    for (int mf = 0; mf < 2; mf++) {
        rs0[mf] += __shfl_xor_sync(0xffffffffu, rs0[mf], 1);
        rs0[mf] += __shfl_xor_sync(0xffffffffu, rs0[mf], 2);
        rs1[mf] += __shfl_xor_sync(0xffffffffu, rs1[mf], 1);
        rs1[mf] += __shfl_xor_sync(0xffffffffu, rs1[mf], 2);
    }
    if ((lane & 3) == 0) {
#pragma unroll
        for (int mf = 0; mf < 2; mf++) {
            s_red[rb[mf] * 4 + wn] = rs0[mf];
            s_red[(rb[mf] + 8) * 4 + wn] = rs1[mf];
        }
    }
    CP_WAIT0();           // vdT in
    __syncthreads();      // s_red + Pstage + vdT visible

    // g_inv for osal
    if (tid < 64) {
        int mm = mBase + tid, il = mm >> 2, h = mm & 3;
        if (il < L) {
            float s4 = s_red[tid * 4] + s_red[tid * 4 + 1] + s_red[tid * 4 + 2] + s_red[tid * 4 + 3];
            g_inv[(size_t)(s0 + il) * NH + 4 * g + h] = 1.f / s4;
        }
    }

    // delta PV: Pstage (A) @ vdT (B), k = 128 salient
    float pv[2][4][4];
#pragma unroll
    for (int a = 0; a < 2; a++)
#pragma unroll
        for (int b = 0; b < 4; b++)
#pragma unroll
            for (int c = 0; c < 4; c++) pv[a][b][c] = 0.f;
    hmma_AB(sb, PST, 0u, pv, wid, lane);

    // output: non-salient rows only (salient rows overwritten by k_pv)
#pragma unroll
    for (int mf = 0; mf < 2; mf++) {
        int r0 = rb[mf], r1 = r0 + 8;
        int mr0 = mBase + r0, mr1 = mBase + r1;
        int il0 = mr0 >> 2, h0 = mr0 & 3;
        int il1 = mr1 >> 2, h1 = mr1 & 3;
        bool w0 = (il0 < L) && (g_salpos[s0 + il0] < 0);
        bool w1 = (il1 < L) && (g_salpos[s0 + il1] < 0);
        float inv0 = 0.f, inv1 = 0.f;
        if (w0) inv0 = 1.f / (s_red[r0 * 4] + s_red[r0 * 4 + 1] + s_red[r0 * 4 + 2] + s_red[r0 * 4 + 3]);
        if (w1) inv1 = 1.f / (s_red[r1 * 4] + s_red[r1 * 4 + 1] + s_red[r1 * 4 + 2] + s_red[r1 * 4 + 3]);
        size_t id0 = (size_t)(s0 + il0) * NH + 4 * g + h0;
        size_t id1 = (size_t)(s0 + il1) * NH + 4 * g + h1;
#pragma unroll
        for (int nf = 0; nf < 4; nf++) {
            int dcol = wn * 32 + nf * 8 + (lane & 3) * 2;
            float* c = pv[mf][nf];
            if (w0) {
                size_t ob = id0 * HD + dcol;
                float2 cv = *(const float2*)(cc + ob);
                *(float2*)(outc + ob) = make_float2(cv.x + inv0 * c[0], cv.y + inv0 * c[1]);
            }
            if (w1) {
                size_t ob = id1 * HD + dcol;
                float2 cv = *(const float2*)(cc + ob);
                *(float2*)(outc + ob) = make_float2(cv.x + inv1 * c[2], cv.y + inv1 * c[3]);
            }
        }
    }
}

// ---------------- K2: osal only: salient rows out = inv * (Posal @ vnT) ----------------
__global__ void __launch_bounds__(256, 2) k_pv(float* __restrict__ outc) {
    extern __shared__ char dsm[];
    const int sg = blockIdx.y;
    const int s = sg >> 3, g = sg & 7;
    const int s0 = g_cu[s];
    const int L = g_cu[s + 1] - s0;
    const int salst = g_salst[s], salcnt = g_salcnt[s];

    const int tid = threadIdx.x, wid = tid >> 5, lane = tid & 31;
    const int wm = wid >> 2, wn = wid & 3;
    const uint32_t sb = smem_to_u32(dsm);

    const int mBase = blockIdx.x * 64;
    if (mBase >= 4 * salcnt) return;

    float acc[2][4][4];
#pragma unroll
    for (int a = 0; a < 2; a++)
#pragma unroll
        for (int b = 0; b < 4; b++)
#pragma unroll
            for (int c = 0; c < 4; c++) acc[a][b][c] = 0.f;

    for (int kc = 0; kc * 128 < L; kc++) {
#pragma unroll
        for (int it = 0; it < 4; it++) {
            int idx = tid + it * 256;
            int r = idx >> 4, ch = idx & 15;
            uint32_t d = (uint32_t)(r * 256) + (((uint32_t)(ch ^ (r & 7))) << 4);
            int m = mBase + r, saloc = m >> 2, hh = m & 3;
            int kk = kc * 128 + ch * 8;
            bool va = (saloc < salcnt) && (kk < L);
            size_t ia = va ? (((size_t)(salst + saloc) * NH + 4 * g + hh) * SMAXK + kk) : 0;
            cpa16(sb + d, g_Posal_hi + ia, va);
            cpa16(sb + A_LO + d, g_Posal_lo + ia, va);
        }
#pragma unroll
        for (int it = 0; it < 8; it++) {
            int idx = tid + it * 256;
            int r = idx >> 4, ch = idx & 15;
            uint32_t d = (uint32_t)(r * 256) + (((uint32_t)(ch ^ (r & 7))) << 4);
            int kk = kc * 128 + ch * 8;
            bool vb = (kk < L);
            size_t ib = vb ? (((size_t)(g * HD + r)) * TT + s0 + kk) : 0;
            cpa16(sb + B_HI + d, g_vnT_hi + ib, vb);
            cpa16(sb + B_HI + 32768u + d, g_vnT_lo + ib, vb);
        }
        CP_COMMIT();
        CP_WAIT0();
        __syncthreads();
        hmma_AB(sb, 0u, B_HI, acc, wid, lane);
        __syncthreads();
    }

#pragma unroll
    for (int mf = 0; mf < 2; mf++) {
        int mr0 = mBase + wm * 32 + mf * 16 + (lane >> 2);
        int mr1 = mr0 + 8;
        int sa0 = mr0 >> 2, h0 = mr0 & 3;
        int sa1 = mr1 >> 2, h1 = mr1 & 3;
        bool ok0 = sa0 < salcnt, ok1 = sa1 < salcnt;
        size_t id0 = 0, id1 = 0;
        float inv0 = 0.f, inv1 = 0.f;
        if (ok0) { id0 = (size_t)g_idx[salst + sa0] * NH + 4 * g + h0; inv0 = g_inv[id0]; }
        if (ok1) { id1 = (size_t)g_idx[salst + sa1] * NH + 4 * g + h1; inv1 = g_inv[id1]; }
#pragma unroll
        for (int nf = 0; nf < 4; nf++) {
            int dcol = wn * 32 + nf * 8 + (lane & 3) * 2;
            float* c = acc[mf][nf];
            if (ok0) *(float2*)(outc + id0 * HD + dcol) = make_float2(inv0 * c[0], inv0 * c[1]);
            if (ok1) *(float2*)(outc + id1 * HD + dcol) = make_float2(inv1 * c[2], inv1 * c[3]);
        }
    }
}

// ---------------- K3: per-row cosine similarity (warp-shuffle reduction) ----------------
__global__ void __launch_bounds__(512) k_cos(const float* __restrict__ cc, const float* __restrict__ outc,
                                             float* __restrict__ cosv) {
    const int tid = threadIdx.x, wid = tid >> 5, lane = tid & 31;
    size_t base = (size_t)blockIdx.x * (NH * HD);
    const float4* a4 = (const float4*)(cc + base);
    const float4* b4 = (const float4*)(outc + base);
    float ab = 0.f, aa = 0.f, bb = 0.f;
#pragma unroll
    for (int j = 0; j < 2; j++) {
        float4 x = a4[tid + j * 512], y = b4[tid + j * 512];
        ab += x.x * y.x + x.y * y.y + x.z * y.z + x.w * y.w;
        aa += x.x * x.x + x.y * x.y + x.z * x.z + x.w * x.w;
        bb += y.x * y.x + y.y * y.y + y.z * y.z + y.w * y.w;
    }
#pragma unroll
    for (int o = 16; o; o >>= 1) {
        ab += __shfl_xor_sync(0xffffffffu, ab, o);
        aa += __shfl_xor_sync(0xffffffffu, aa, o);
        bb += __shfl_xor_sync(0xffffffffu, bb, o);
    }
    __shared__ float sh[3][16];
    if (lane == 0) { sh[0][wid] = ab; sh[1][wid] = aa; sh[2][wid] = bb; }
    __syncthreads();
    if (tid < 32) {
        float a2 = (tid < 16) ? sh[0][tid] : 0.f;
        float b2 = (tid < 16) ? sh[1][tid] : 0.f;
        float c2 = (tid < 16) ? sh[2][tid] : 0.f;
#pragma unroll
        for (int o = 8; o; o >>= 1) {
            a2 += __shfl_xor_sync(0xffffffffu, a2, o);
            b2 += __shfl_xor_sync(0xffffffffu, b2, o);
            c2 += __shfl_xor_sync(0xffffffffu, c2, o);
        }
        if (tid == 0)
            cosv[blockIdx.x] = a2 / (sqrtf(b2) * sqrtf(c2) + 1e-8f);
    }
}

// ---------------- launch ----------------
extern "C" void kernel_launch(void* const* d_in, const int* in_sizes, int n_in,
                              void* d_out, int out_size) {
    const float* q       = (const float*)d_in[0];
    const float* k       = (const float*)d_in[1];
    const float* v       = (const float*)d_in[2];
    const float* v_cache = (const float*)d_in[3];
    const float* c_cache = (const float*)d_in[4];
    const void*  idx     = d_in[5];
    const void*  cu      = d_in[6];

    float* outc = (float*)d_out;
    float* cosv = outc + (size_t)(out_size - TT);

    cudaFuncSetAttribute(k_qk,  cudaFuncAttributeMaxDynamicSharedMemorySize, 98304);
    cudaFuncSetAttribute(k_pv,  cudaFuncAttributeMaxDynamicSharedMemorySize, 98304);
    cudaFuncSetAttribute(k_pre, cudaFuncAttributeMaxDynamicSharedMemorySize, 16512);

    k_prep<<<1, 256>>>(idx, cu);
    k_pre<<<CVT_BLKS + VN_BLKS + VD_BLKS, 256, 16512>>>(q, k, v, v_cache);
    k_qk<<<dim3(32, 32), 256, 98304>>>(c_cache, outc);
    k_pv<<<dim3(8, 32), 256, 98304>>>(outc);
    k_cos<<<TT, 512>>>(c_cache, outc, cosv);
}

// round 11
// speedup vs baseline: 1.1224x; 1.0033x over previous
#include <cuda_runtime.h>
#include <cuda_bf16.h>
#include <math.h>
#include <stdint.h>

typedef unsigned long long ull;
typedef long long ll;

#define TT    2048
#define NH    32
#define NKV   8
#define HD    128
#define NSALT 512
#define NSEG  4
#define SMAXK 512
#define SCALE_L2E 0.12751742788f   /* (1/sqrt(128)) * log2(e) */

#define CVT_BLKS 2048   /* K only: 2048*8*128/4/256 */
#define VN_BLKS  512
#define VD_BLKS  128

// k_qk smem (96KB): Q_hi[0,16K) Q_lo[16K,32K) K_hi[32K,48K) K_lo[48K,64K) Pst_hi[64K,80K) Pst_lo[80K,96K)
// PV phase reuses: vdT_hi -> [0,32K), vdT_lo -> [32K,64K)
#define KOFF 32768u
#define PST  65536u
// k_pv smem (96KB): A_hi[0,16K) A_lo[16K,32K) B_hi[32K,64K) B_lo[64K,96K)
#define A_LO 16384u
#define B_HI 32768u

// ---------------- scratch (device globals: allocation-free) ----------------
__device__ float g_inv[(size_t)TT * NH];
__device__ __nv_bfloat16 g_khi[(size_t)TT * NKV * HD];
__device__ __nv_bfloat16 g_klo[(size_t)TT * NKV * HD];
__device__ __nv_bfloat16 g_Posal_hi[(size_t)NSALT * NH * SMAXK];
__device__ __nv_bfloat16 g_Posal_lo[(size_t)NSALT * NH * SMAXK];
__device__ __nv_bfloat16 g_vnT_hi[(size_t)NKV * HD * TT];
__device__ __nv_bfloat16 g_vnT_lo[(size_t)NKV * HD * TT];
__device__ __nv_bfloat16 g_vdT_hi[(size_t)NKV * HD * NSALT];
__device__ __nv_bfloat16 g_vdT_lo[(size_t)NKV * HD * NSALT];
__device__ int   g_idx[NSALT];
__device__ int   g_cu[NSEG + 1];
__device__ int   g_salpos[TT];
__device__ int   g_salst[NSEG];
__device__ int   g_salcnt[NSEG];

// ---------------- helpers ----------------
__device__ __forceinline__ uint32_t smem_to_u32(const void* p) {
    uint32_t a;
    asm("{ .reg .u64 t; cvta.to.shared.u64 t, %1; cvt.u32.u64 %0, t; }" : "=r"(a) : "l"(p));
    return a;
}
__device__ __forceinline__ void ldsm4(uint32_t* r, uint32_t addr) {
    asm volatile("ldmatrix.sync.aligned.m8n8.x4.shared.b16 {%0,%1,%2,%3}, [%4];"
        : "=r"(r[0]), "=r"(r[1]), "=r"(r[2]), "=r"(r[3]) : "r"(addr));
}
__device__ __forceinline__ void mma16816(float* c, const uint32_t* a, uint32_t b0, uint32_t b1) {
    asm volatile("mma.sync.aligned.m16n8k16.row.col.f32.bf16.bf16.f32 "
        "{%0,%1,%2,%3}, {%4,%5,%6,%7}, {%8,%9}, {%0,%1,%2,%3};"
        : "+f"(c[0]), "+f"(c[1]), "+f"(c[2]), "+f"(c[3])
        : "r"(a[0]), "r"(a[1]), "r"(a[2]), "r"(a[3]), "r"(b0), "r"(b1));
}
__device__ __forceinline__ void cpa16(uint32_t dst, const void* src, bool valid) {
    int sz = valid ? 16 : 0;
    asm volatile("cp.async.cg.shared.global [%0], [%1], 16, %2;"
        :: "r"(dst), "l"(src), "r"(sz) : "memory");
}
#define CP_COMMIT() asm volatile("cp.async.commit_group;" ::: "memory")
#define CP_WAIT0()  asm volatile("cp.async.wait_group 0;" ::: "memory")

__device__ __forceinline__ float fexp2(float x) {
    float r;
    asm("ex2.approx.f32 %0, %1;" : "=f"(r) : "f"(x));
    return r;
}
__device__ __forceinline__ void bf_split(float x, __nv_bfloat16& h, __nv_bfloat16& l) {
    h = __float2bfloat16(x);
    l = __float2bfloat16(x - __bfloat162float(h));
}

// 64(m)x128(n)x128(k) 3-pass HMMA: A hi@aOff, lo@aOff+16K; B hi@bOff, lo@bOff+32K.
// Rows 256B, 16B-chunk XOR swizzle. 8 warps = 2(m) x 4(n). (Verified rounds 4-10.)
__device__ __forceinline__ void hmma_AB(uint32_t sb, uint32_t aOff, uint32_t bOff,
                                        float acc[2][4][4], int wid, int lane) {
    const int wm = wid >> 2, wn = wid & 3;
    uint32_t a_ad[2], a_rx[2];
#pragma unroll
    for (int mf = 0; mf < 2; mf++) {
        int row = wm * 32 + mf * 16 + (lane & 15);
        a_ad[mf] = sb + aOff + row * 256;
        a_rx[mf] = ((uint32_t)(row & 7)) << 4;
    }
    const int achunk = (lane >> 4);
    uint32_t b_ad[2], b_rx[2];
#pragma unroll
    for (int bg = 0; bg < 2; bg++) {
        int n = wn * 32 + bg * 16 + (lane & 7) + ((lane >> 4) << 3);
        b_ad[bg] = sb + bOff + n * 256;
        b_rx[bg] = ((uint32_t)(n & 7)) << 4;
    }
    const int bchunk = (lane >> 3) & 1;
#pragma unroll
    for (int ks = 0; ks < 8; ks++) {
        uint32_t ah[2][4], al[2][4];
#pragma unroll
        for (int mf = 0; mf < 2; mf++) {
            uint32_t coff = (((uint32_t)(ks * 2 + achunk)) << 4) ^ a_rx[mf];
            ldsm4(ah[mf], a_ad[mf] + coff);
            ldsm4(al[mf], a_ad[mf] + 16384u + coff);
        }
        uint32_t bh[2][4], bl[2][4];
#pragma unroll
        for (int bg = 0; bg < 2; bg++) {
            uint32_t coff = (((uint32_t)(ks * 2 + bchunk)) << 4) ^ b_rx[bg];
            ldsm4(bh[bg], b_ad[bg] + coff);
            ldsm4(bl[bg], b_ad[bg] + 32768u + coff);
        }
#pragma unroll
        for (int mf = 0; mf < 2; mf++)
#pragma unroll
            for (int nf = 0; nf < 4; nf++) {
                int bg = nf >> 1, sel = (nf & 1) * 2;
                mma16816(acc[mf][nf], ah[mf], bh[bg][sel], bh[bg][sel + 1]);
                mma16816(acc[mf][nf], ah[mf], bl[bg][sel], bl[bg][sel + 1]);
                mma16816(acc[mf][nf], al[mf], bh[bg][sel], bh[bg][sel + 1]);
            }
    }
}

// 64(m)x64(n)x128(k) 3-pass HMMA (QK phase). A hi@0, lo@16K; B hi@KOFF, lo@KOFF+16K.
__device__ __forceinline__ void hmma_64(uint32_t sb, float acc[2][2][4], int wid, int lane) {
    const int wm = wid >> 2, wn = wid & 3;
    uint32_t a_ad[2], a_rx[2];
#pragma unroll
    for (int mf = 0; mf < 2; mf++) {
        int row = wm * 32 + mf * 16 + (lane & 15);
        a_ad[mf] = sb + row * 256;
        a_rx[mf] = ((uint32_t)(row & 7)) << 4;
    }
    const int achunk = (lane >> 4);
    int n = wn * 16 + (lane & 7) + ((lane >> 4) << 3);
    uint32_t b_ad = sb + KOFF + n * 256;
    uint32_t b_rx = ((uint32_t)(n & 7)) << 4;
    const int bchunk = (lane >> 3) & 1;
#pragma unroll
    for (int ks = 0; ks < 8; ks++) {
        uint32_t ah[2][4], al[2][4];
#pragma unroll
        for (int mf = 0; mf < 2; mf++) {
            uint32_t coff = (((uint32_t)(ks * 2 + achunk)) << 4) ^ a_rx[mf];
            ldsm4(ah[mf], a_ad[mf] + coff);
            ldsm4(al[mf], a_ad[mf] + 16384u + coff);
        }
        uint32_t bh[4], bl[4];
        {
            uint32_t coff = (((uint32_t)(ks * 2 + bchunk)) << 4) ^ b_rx;
            ldsm4(bh, b_ad + coff);
            ldsm4(bl, b_ad + 16384u + coff);
        }
#pragma unroll
        for (int mf = 0; mf < 2; mf++)
#pragma unroll
            for (int nf = 0; nf < 2; nf++) {
                int sel = nf * 2;
                mma16816(acc[mf][nf], ah[mf], bh[sel], bh[sel + 1]);
                mma16816(acc[mf][nf], ah[mf], bl[sel], bl[sel + 1]);
                mma16816(acc[mf][nf], al[mf], bh[sel], bh[sel + 1]);
            }
    }
}

// store one P value (hi+lo planes) into swizzled Pstage
__device__ __forceinline__ void sts_p(char* dsm, int row, int salcol, float val) {
    __nv_bfloat16 h, l;
    bf_split(val, h, l);
    uint32_t off = (uint32_t)row * 256 + ((((uint32_t)(salcol >> 3)) ^ (uint32_t)(row & 7)) << 4)
                 + (uint32_t)((2 * salcol) & 15);
    *(__nv_bfloat16*)(dsm + PST + off) = h;
    *(__nv_bfloat16*)(dsm + PST + 16384u + off) = l;
}

// ---------------- K0a: decode indices, segment tables ----------------
__global__ void k_prep(const void* idx_raw, const void* cu_raw) {
    const int* i32 = (const int*)idx_raw;
    const int* c32 = (const int*)cu_raw;
    const bool idx64 = (i32[1] == 0);
    const bool cu64  = (c32[1] == 0);
    const int t = threadIdx.x;

    for (int i = t; i < NSALT; i += 256)
        g_idx[i] = idx64 ? (int)((const long long*)idx_raw)[i] : i32[i];
    if (t <= NSEG)
        g_cu[t] = cu64 ? (int)((const long long*)cu_raw)[t] : c32[t];
    for (int i = t; i < TT; i += 256) g_salpos[i] = -1;
    __syncthreads();
    for (int i = t; i < NSALT; i += 256) g_salpos[g_idx[i]] = i;
    if (t == 0) {
        for (int s = 0; s < NSEG; s++) {
            int a = 0;
            while (a < NSALT && g_idx[a] < g_cu[s]) a++;
            int b = a;
            while (b < NSALT && g_idx[b] < g_cu[s + 1]) b++;
            g_salst[s] = a;
            g_salcnt[s] = b - a;
        }
    }
}

// ---------------- K0b (merged): K cvt || build_vn || build_vd ----------------
__global__ void __launch_bounds__(256) k_pre(const float* __restrict__ kk,
                                             const float* __restrict__ v, const float* __restrict__ vc) {
    extern __shared__ float tile[];   // [32][129]
    const int bx = blockIdx.x;
    const int tid = threadIdx.x;

    if (bx < CVT_BLKS) {
        int i = bx * 256 + tid;     // float4 index into k
        float4 x = ((const float4*)kk)[i];
        __nv_bfloat162* h2 = (__nv_bfloat162*)g_khi + 2 * (size_t)i;
        __nv_bfloat162* l2 = (__nv_bfloat162*)g_klo + 2 * (size_t)i;
        __nv_bfloat162 a = __float22bfloat162_rn(make_float2(x.x, x.y));
        __nv_bfloat162 b = __float22bfloat162_rn(make_float2(x.z, x.w));
        __nv_bfloat162 al = __float22bfloat162_rn(make_float2(x.x - __low2float(a), x.y - __high2float(a)));
        __nv_bfloat162 bl = __float22bfloat162_rn(make_float2(x.z - __low2float(b), x.w - __high2float(b)));
        h2[0] = a; h2[1] = b; l2[0] = al; l2[1] = bl;
        return;
    }

    if (bx < CVT_BLKS + VN_BLKS) {
        int t2 = bx - CVT_BLKS;
        int kc = t2 >> 3, g = t2 & 7;
#pragma unroll
        for (int it = 0; it < 4; it++) {
            int fi = tid + it * 256;
            int key = fi >> 5, c4 = fi & 31;
            int gk = kc * 32 + key;
            int sp = g_salpos[gk];
            const float* src = (sp >= 0) ? v + ((size_t)sp * NKV + g) * HD + c4 * 4
                                         : vc + ((size_t)gk * NKV + g) * HD + c4 * 4;
            float4 x = *(const float4*)src;
            float* tr = tile + key * 129 + c4 * 4;
            tr[0] = x.x; tr[1] = x.y; tr[2] = x.z; tr[3] = x.w;
        }
        __syncthreads();
#pragma unroll
        for (int it = 0; it < 8; it++) {
            int wi = tid + it * 256;
            int d = wi >> 4, kp = wi & 15;
            float v0 = tile[(2 * kp) * 129 + d], v1 = tile[(2 * kp + 1) * 129 + d];
            __nv_bfloat16 h0, l0, h1, l1;
            bf_split(v0, h0, l0); bf_split(v1, h1, l1);
            __nv_bfloat162 ph; ph.x = h0; ph.y = h1;
            __nv_bfloat162 pl; pl.x = l0; pl.y = l1;
            size_t dst = ((size_t)g * HD + d) * TT + kc * 32 + 2 * kp;
            *(__nv_bfloat162*)(g_vnT_hi + dst) = ph;
            *(__nv_bfloat162*)(g_vnT_lo + dst) = pl;
        }
        return;
    }

    {
        int t2 = bx - CVT_BLKS - VN_BLKS;
        int kc = t2 >> 3, g = t2 & 7;
#pragma unroll
        for (int it = 0; it < 4; it++) {
            int fi = tid + it * 256;
            int sidx = fi >> 5, c4 = fi & 31;
            int sal = kc * 32 + sidx;
            const float* pv = v  + ((size_t)sal * NKV + g) * HD + c4 * 4;
            const float* pc = vc + ((size_t)g_idx[sal] * NKV + g) * HD + c4 * 4;
            float4 a = *(const float4*)pv;
            float4 b = *(const float4*)pc;
            float* tr = tile + sidx * 129 + c4 * 4;
            tr[0] = a.x - b.x; tr[1] = a.y - b.y; tr[2] = a.z - b.z; tr[3] = a.w - b.w;
        }
        __syncthreads();
#pragma unroll
        for (int it = 0; it < 8; it++) {
            int wi = tid + it * 256;
            int d = wi >> 4, kp = wi & 15;
            float v0 = tile[(2 * kp) * 129 + d], v1 = tile[(2 * kp + 1) * 129 + d];
            __nv_bfloat16 h0, l0, h1, l1;
            bf_split(v0, h0, l0); bf_split(v1, h1, l1);
            __nv_bfloat162 ph; ph.x = h0; ph.y = h1;
            __nv_bfloat162 pl; pl.x = l0; pl.y = l1;
            size_t dst = ((size_t)g * HD + d) * NSALT + kc * 32 + 2 * kp;
            *(__nv_bfloat162*)(g_vdT_hi + dst) = ph;
            *(__nv_bfloat162*)(g_vdT_lo + dst) = pl;
        }
    }
}

// ---------------- K1: fused QK^T + exp + rowsum + delta-PV (inline Q split) ----------------
__device__ __forceinline__ void qk_loadK(uint32_t sb, int tid, int nt, int s0, int L, int g) {
#pragma unroll
    for (int it = 0; it < 4; it++) {
        int idx = tid + it * 256;
        int r = idx >> 4, ch = idx & 15;
        uint32_t d = (uint32_t)(r * 256) + (((uint32_t)(ch ^ (r & 7))) << 4);
        int jg = nt * 64 + r;
        bool v = jg < L;
        size_t o = v ? (((size_t)(s0 + jg) * NKV + g) * HD + ch * 8) : 0;
        cpa16(sb + KOFF + d, g_khi + o, v);
        cpa16(sb + KOFF + 16384u + d, g_klo + o, v);
    }
}

__global__ void __launch_bounds__(256, 2) k_qk(const float* __restrict__ qf,
                                               const float* __restrict__ cc, float* __restrict__ outc) {
    extern __shared__ char dsm[];
    __shared__ int s_sp[SMAXK];
    __shared__ float s_red[64 * 4];
    const int sg = blockIdx.y;
    const int s = sg >> 3, g = sg & 7;
    const int s0 = g_cu[s];
    const int L = g_cu[s + 1] - s0;
    const int mBase = blockIdx.x * 64;
    if (mBase >= 4 * L) return;
    const int salst = g_salst[s], salcnt = g_salcnt[s];

    const int tid = threadIdx.x, wid = tid >> 5, lane = tid & 31;
    const int wm = wid >> 2, wn = wid & 3;
    const uint32_t sb = smem_to_u32(dsm);

    // K tile 0 in flight first
    qk_loadK(sb, tid, 0, s0, L, g);
    CP_COMMIT();

    for (int j = tid; j < L; j += 256) {
        int sp = g_salpos[s0 + j];
        s_sp[j] = sp >= 0 ? sp - salst : -1;
    }

    // zero Pstage (32KB)
    {
        uint4 z = make_uint4(0, 0, 0, 0);
#pragma unroll
        for (int it = 0; it < 8; it++)
            *(uint4*)(dsm + PST + (size_t)(tid + it * 256) * 16) = z;
    }

    // Q tile: fp32 global -> bf16 hi/lo split -> swizzled STS (exact, same math as old k_pre)
#pragma unroll
    for (int it = 0; it < 4; it++) {
        int idx = tid + it * 256;
        int r = idx >> 4, ch = idx & 15;
        uint32_t d = (uint32_t)(r * 256) + (((uint32_t)(ch ^ (r & 7))) << 4);
        int mm = mBase + r, il = mm >> 2, hh = mm & 3;
        __nv_bfloat162 h2[4], l2[4];
        if (il < L) {
            const float4* src = (const float4*)(qf + ((size_t)(s0 + il) * NH + 4 * g + hh) * HD + ch * 8);
            float4 x0 = src[0], x1 = src[1];
            float xs[8] = {x0.x, x0.y, x0.z, x0.w, x1.x, x1.y, x1.z, x1.w};
#pragma unroll
            for (int e = 0; e < 4; e++) {
                __nv_bfloat16 ha, la, hb, lb;
                bf_split(xs[2 * e], ha, la);
                bf_split(xs[2 * e + 1], hb, lb);
                h2[e].x = ha; h2[e].y = hb;
                l2[e].x = la; l2[e].y = lb;
            }
        } else {
#pragma unroll
            for (int e = 0; e < 4; e++) {
                h2[e] = __nv_bfloat162();
                l2[e] = __nv_bfloat162();
            }
        }
        *(uint4*)(dsm + d) = *(uint4*)h2;
        *(uint4*)(dsm + 16384u + d) = *(uint4*)l2;
    }

    // per-row metadata (Posal base for salient rows)
    ll pb0[2], pb1[2];
    bool ok0[2], ok1[2];
    int rb[2];
#pragma unroll
    for (int mf = 0; mf < 2; mf++) {
        rb[mf] = wm * 32 + mf * 16 + (lane >> 2);
        int mr0 = mBase + rb[mf];
        int mr1 = mr0 + 8;
        int il0 = mr0 >> 2, h0 = mr0 & 3;
        int il1 = mr1 >> 2, h1 = mr1 & 3;
        ok0[mf] = il0 < L; ok1[mf] = il1 < L;
        int sp0 = ok0[mf] ? g_salpos[s0 + il0] : -1;
        int sp1 = ok1[mf] ? g_salpos[s0 + il1] : -1;
        pb0[mf] = sp0 >= 0 ? ((ll)sp0 * NH + 4 * g + h0) * SMAXK : -1;
        pb1[mf] = sp1 >= 0 ? ((ll)sp1 * NH + 4 * g + h1) * SMAXK : -1;
    }

    float rs0[2] = {0.f, 0.f}, rs1[2] = {0.f, 0.f};

    for (int nt = 0; nt < 8; nt++) {
        CP_WAIT0();
        __syncthreads();

        float acc[2][2][4];
#pragma unroll
        for (int a = 0; a < 2; a++)
#pragma unroll
            for (int b = 0; b < 2; b++)
#pragma unroll
                for (int c = 0; c < 4; c++) acc[a][b][c] = 0.f;

        hmma_64(sb, acc, wid, lane);
        __syncthreads();   // K (and on last tile, Q) now dead
        if (nt < 7) {
            qk_loadK(sb, tid, nt + 1, s0, L, g);
            CP_COMMIT();
        } else {
            // vdT tile: hi -> [0,32K), lo -> [32K,64K): [128 d][128 sal]
#pragma unroll
            for (int it = 0; it < 8; it++) {
                int idx = tid + it * 256;
                int r = idx >> 4, ch = idx & 15;
                uint32_t d = (uint32_t)(r * 256) + (((uint32_t)(ch ^ (r & 7))) << 4);
                bool vb = (ch * 8 < salcnt);
                size_t ib = vb ? (((size_t)(g * HD + r)) * NSALT + salst + ch * 8) : 0;
                cpa16(sb + d, g_vdT_hi + ib, vb);
                cpa16(sb + 32768u + d, g_vdT_lo + ib, vb);
            }
            CP_COMMIT();
        }

        // epilogue: exp, rowsum, Pstage STS (salient cols), Posal STG (salient rows)
#pragma unroll
        for (int nf = 0; nf < 2; nf++) {
            int col = nt * 64 + wn * 16 + nf * 8 + (lane & 3) * 2;
            bool c0 = col < L, c1 = col + 1 < L;
            int spa = c0 ? s_sp[col] : -1;
            int spb = c1 ? s_sp[col + 1] : -1;
#pragma unroll
            for (int mf = 0; mf < 2; mf++) {
                float* c = acc[mf][nf];
                float e0 = (ok0[mf] && c0) ? fexp2(c[0] * SCALE_L2E) : 0.f;
                float e1 = (ok0[mf] && c1) ? fexp2(c[1] * SCALE_L2E) : 0.f;
                float e2 = (ok1[mf] && c0) ? fexp2(c[2] * SCALE_L2E) : 0.f;
                float e3 = (ok1[mf] && c1) ? fexp2(c[3] * SCALE_L2E) : 0.f;
                rs0[mf] += e0 + e1;
                rs1[mf] += e2 + e3;
                int r0 = rb[mf], r1 = r0 + 8;
                if (spa >= 0) {
                    if (ok0[mf]) sts_p(dsm, r0, spa, e0);
                    if (ok1[mf]) sts_p(dsm, r1, spa, e2);
                }
                if (spb >= 0) {
                    if (ok0[mf]) sts_p(dsm, r0, spb, e1);
                    if (ok1[mf]) sts_p(dsm, r1, spb, e3);
                }
                if (pb0[mf] >= 0 && c0) {
                    __nv_bfloat16 h0, l0, h1, l1;
                    bf_split(e0, h0, l0); bf_split(e1, h1, l1);
                    __nv_bfloat162 ph; ph.x = h0; ph.y = h1;
                    __nv_bfloat162 pl; pl.x = l0; pl.y = l1;
                    *(__nv_bfloat162*)(g_Posal_hi + pb0[mf] + col) = ph;
                    *(__nv_bfloat162*)(g_Posal_lo + pb0[mf] + col) = pl;
                }
                if (pb1[mf] >= 0 && c0) {
                    __nv_bfloat16 h0, l0, h1, l1;
                    bf_split(e2, h0, l0); bf_split(e3, h1, l1);
                    __nv_bfloat162 ph; ph.x = h0; ph.y = h1;
                    __nv_bfloat162 pl; pl.x = l0; pl.y = l1;
                    *(__nv_bfloat162*)(g_Posal_hi + pb1[mf] + col) = ph;
                    *(__nv_bfloat162*)(g_Posal_lo + pb1[mf] + col) = pl;
                }
            }
        }
    }

    // rowsum reduction across n-warps
#pragma unroll
    for (int mf = 0; mf < 2; mf++) {
        rs0[mf] += __shfl_xor_sync(0xffffffffu, rs0[mf], 1);
        rs0[mf] += __shfl_xor_sync(0xffffffffu, rs0[mf], 2);
        rs1[mf] += __shfl_xor_sync(0xffffffffu, rs1[mf], 1);
        rs1[mf] += __shfl_xor_sync(0xffffffffu, rs1[mf], 2);
    }
    if ((lane & 3) == 0) {
#pragma unroll
        for (int mf = 0; mf < 2; mf++) {
            s_red[rb[mf] * 4 + wn] = rs0[mf];
            s_red[(rb[mf] + 8) * 4 + wn] = rs1[mf];
        }
    }
    CP_WAIT0();           // vdT in
    __syncthreads();      // s_red + Pstage + vdT visible

    // g_inv for osal
    if (tid < 64) {
        int mm = mBase + tid, il = mm >> 2, h = mm & 3;
        if (il < L) {
            float s4 = s_red[tid * 4] + s_red[tid * 4 + 1] + s_red[tid * 4 + 2] + s_red[tid * 4 + 3];
            g_inv[(size_t)(s0 + il) * NH + 4 * g + h] = 1.f / s4;
        }
    }

    // delta PV: Pstage (A) @ vdT (B), k = 128 salient
    float pv[2][4][4];
#pragma unroll
    for (int a = 0; a < 2; a++)
#pragma unroll
        for (int b = 0; b < 4; b++)
#pragma unroll
            for (int c = 0; c < 4; c++) pv[a][b][c] = 0.f;
    hmma_AB(sb, PST, 0u, pv, wid, lane);

    // output: non-salient rows only (salient rows overwritten by k_pv)
#pragma unroll
    for (int mf = 0; mf < 2; mf++) {
        int r0 = rb[mf], r1 = r0 + 8;
        int mr0 = mBase + r0, mr1 = mBase + r1;
        int il0 = mr0 >> 2, h0 = mr0 & 3;
        int il1 = mr1 >> 2, h1 = mr1 & 3;
        bool w0 = (il0 < L) && (g_salpos[s0 + il0] < 0);
        bool w1 = (il1 < L) && (g_salpos[s0 + il1] < 0);
        float inv0 = 0.f, inv1 = 0.f;
        if (w0) inv0 = 1.f / (s_red[r0 * 4] + s_red[r0 * 4 + 1] + s_red[r0 * 4 + 2] + s_red[r0 * 4 + 3]);
        if (w1) inv1 = 1.f / (s_red[r1 * 4] + s_red[r1 * 4 + 1] + s_red[r1 * 4 + 2] + s_red[r1 * 4 + 3]);
        size_t id0 = (size_t)(s0 + il0) * NH + 4 * g + h0;
        size_t id1 = (size_t)(s0 + il1) * NH + 4 * g + h1;
#pragma unroll
        for (int nf = 0; nf < 4; nf++) {
            int dcol = wn * 32 + nf * 8 + (lane & 3) * 2;
            float* c = pv[mf][nf];
            if (w0) {
                size_t ob = id0 * HD + dcol;
                float2 cv = *(const float2*)(cc + ob);
                *(float2*)(outc + ob) = make_float2(cv.x + inv0 * c[0], cv.y + inv0 * c[1]);
            }
            if (w1) {
                size_t ob = id1 * HD + dcol;
                float2 cv = *(const float2*)(cc + ob);
                *(float2*)(outc + ob) = make_float2(cv.x + inv1 * c[2], cv.y + inv1 * c[3]);
            }
        }
    }
}

// ---------------- K2: osal only: salient rows out = inv * (Posal @ vnT) ----------------
__global__ void __launch_bounds__(256, 2) k_pv(float* __restrict__ outc) {
    extern __shared__ char dsm[];
    const int sg = blockIdx.y;
    const int s = sg >> 3, g = sg & 7;
    const int s0 = g_cu[s];
    const int L = g_cu[s + 1] - s0;
    const int salst = g_salst[s], salcnt = g_salcnt[s];

    const int tid = threadIdx.x, wid = tid >> 5, lane = tid & 31;
    const int wm = wid >> 2, wn = wid & 3;
    const uint32_t sb = smem_to_u32(dsm);

    const int mBase = blockIdx.x * 64;
    if (mBase >= 4 * salcnt) return;

    float acc[2][4][4];
#pragma unroll
    for (int a = 0; a < 2; a++)
#pragma unroll
        for (int b = 0; b < 4; b++)
#pragma unroll
            for (int c = 0; c < 4; c++) acc[a][b][c] = 0.f;

    for (int kc = 0; kc * 128 < L; kc++) {
#pragma unroll
        for (int it = 0; it < 4; it++) {
            int idx = tid + it * 256;
            int r = idx >> 4, ch = idx & 15;
            uint32_t d = (uint32_t)(r * 256) + (((uint32_t)(ch ^ (r & 7))) << 4);
            int m = mBase + r, saloc = m >> 2, hh = m & 3;
            int kk = kc * 128 + ch * 8;
            bool va = (saloc < salcnt) && (kk < L);
            size_t ia = va ? (((size_t)(salst + saloc) * NH + 4 * g + hh) * SMAXK + kk) : 0;
            cpa16(sb + d, g_Posal_hi + ia, va);
            cpa16(sb + A_LO + d, g_Posal_lo + ia, va);
        }
#pragma unroll
        for (int it = 0; it < 8; it++) {
            int idx = tid + it * 256;
            int r = idx >> 4, ch = idx & 15;
            uint32_t d = (uint32_t)(r * 256) + (((uint32_t)(ch ^ (r & 7))) << 4);
            int kk = kc * 128 + ch * 8;
            bool vb = (kk < L);
            size_t ib = vb ? (((size_t)(g * HD + r)) * TT + s0 + kk) : 0;
            cpa16(sb + B_HI + d, g_vnT_hi + ib, vb);
            cpa16(sb + B_HI + 32768u + d, g_vnT_lo + ib, vb);
        }
        CP_COMMIT();
        CP_WAIT0();
        __syncthreads();
        hmma_AB(sb, 0u, B_HI, acc, wid, lane);
        __syncthreads();
    }

#pragma unroll
    for (int mf = 0; mf < 2; mf++) {
        int mr0 = mBase + wm * 32 + mf * 16 + (lane >> 2);
        int mr1 = mr0 + 8;
        int sa0 = mr0 >> 2, h0 = mr0 & 3;
        int sa1 = mr1 >> 2, h1 = mr1 & 3;
        bool ok0 = sa0 < salcnt, ok1 = sa1 < salcnt;
        size_t id0 = 0, id1 = 0;
        float inv0 = 0.f, inv1 = 0.f;
        if (ok0) { id0 = (size_t)g_idx[salst + sa0] * NH + 4 * g + h0; inv0 = g_inv[id0]; }
        if (ok1) { id1 = (size_t)g_idx[salst + sa1] * NH + 4 * g + h1; inv1 = g_inv[id1]; }
#pragma unroll
        for (int nf = 0; nf < 4; nf++) {
            int dcol = wn * 32 + nf * 8 + (lane & 3) * 2;
            float* c = acc[mf][nf];
            if (ok0) *(float2*)(outc + id0 * HD + dcol) = make_float2(inv0 * c[0], inv0 * c[1]);
            if (ok1) *(float2*)(outc + id1 * HD + dcol) = make_float2(inv1 * c[2], inv1 * c[3]);
        }
    }
}

// ---------------- K3: per-row cosine similarity (warp-shuffle reduction) ----------------
__global__ void __launch_bounds__(512) k_cos(const float* __restrict__ cc, const float* __restrict__ outc,
                                             float* __restrict__ cosv) {
    const int tid = threadIdx.x, wid = tid >> 5, lane = tid & 31;
    size_t base = (size_t)blockIdx.x * (NH * HD);
    const float4* a4 = (const float4*)(cc + base);
    const float4* b4 = (const float4*)(outc + base);
    float ab = 0.f, aa = 0.f, bb = 0.f;
#pragma unroll
    for (int j = 0; j < 2; j++) {
        float4 x = a4[tid + j * 512], y = b4[tid + j * 512];
        ab += x.x * y.x + x.y * y.y + x.z * y.z + x.w * y.w;
        aa += x.x * x.x + x.y * x.y + x.z * x.z + x.w * x.w;
        bb += y.x * y.x + y.y * y.y + y.z * y.z + y.w * y.w;
    }
#pragma unroll
    for (int o = 16; o; o >>= 1) {
        ab += __shfl_xor_sync(0xffffffffu, ab, o);
        aa += __shfl_xor_sync(0xffffffffu, aa, o);
        bb += __shfl_xor_sync(0xffffffffu, bb, o);
    }
    __shared__ float sh[3][16];
    if (lane == 0) { sh[0][wid] = ab; sh[1][wid] = aa; sh[2][wid] = bb; }
    __syncthreads();
    if (tid < 32) {
        float a2 = (tid < 16) ? sh[0][tid] : 0.f;
        float b2 = (tid < 16) ? sh[1][tid] : 0.f;
        float c2 = (tid < 16) ? sh[2][tid] : 0.f;
#pragma unroll
        for (int o = 8; o; o >>= 1) {
            a2 += __shfl_xor_sync(0xffffffffu, a2, o);
            b2 += __shfl_xor_sync(0xffffffffu, b2, o);
            c2 += __shfl_xor_sync(0xffffffffu, c2, o);
        }
        if (tid == 0)
            cosv[blockIdx.x] = a2 / (sqrtf(b2) * sqrtf(c2) + 1e-8f);
    }
}

// ---------------- launch ----------------
extern "C" void kernel_launch(void* const* d_in, const int* in_sizes, int n_in,
                              void* d_out, int out_size) {
    const float* q       = (const float*)d_in[0];
    const float* k       = (const float*)d_in[1];
    const float* v       = (const float*)d_in[2];
    const float* v_cache = (const float*)d_in[3];
    const float* c_cache = (const float*)d_in[4];
    const void*  idx     = d_in[5];
    const void*  cu      = d_in[6];

    float* outc = (float*)d_out;
    float* cosv = outc + (size_t)(out_size - TT);

    cudaFuncSetAttribute(k_qk,  cudaFuncAttributeMaxDynamicSharedMemorySize, 98304);
    cudaFuncSetAttribute(k_pv,  cudaFuncAttributeMaxDynamicSharedMemorySize, 98304);
    cudaFuncSetAttribute(k_pre, cudaFuncAttributeMaxDynamicSharedMemorySize, 16512);

    k_prep<<<1, 256>>>(idx, cu);
    k_pre<<<CVT_BLKS + VN_BLKS + VD_BLKS, 256, 16512>>>(k, v, v_cache);
    k_qk<<<dim3(32, 32), 256, 98304>>>(q, c_cache, outc);
    k_pv<<<dim3(8, 32), 256, 98304>>>(outc);
    k_cos<<<TT, 512>>>(c_cache, outc, cosv);
}

// round 12
// speedup vs baseline: 1.4224x; 1.2673x over previous
#include <cuda_runtime.h>
#include <cuda_fp16.h>
#include <math.h>
#include <stdint.h>

typedef unsigned long long ull;
typedef long long ll;

#define TT    2048
#define NH    32
#define NKV   8
#define HD    128
#define NSALT 512
#define NSEG  4
#define SMAXK 512
#define SCALE_L2E 0.12751742788f   /* (1/sqrt(128)) * log2(e), folded into Q */

#define CVT_BLKS 2048
#define VN_BLKS  512
#define VD_BLKS  128

// k_qk smem (96KB): Q(fp16)[0,16K) Kbuf0[16K,48K){hi,lo} Pst[48K,64K) Kbuf1[64K,96K){hi,lo}
// PV phase: vd_hi -> [16K,48K), vd_lo -> [64K,96K); A = Pst single plane
#define QOFF 0u
#define KB0  16384u
#define PSTO 49152u
#define KB1  65536u
// k_pv smem: A(fp16 single)[0,16K) Bhi[16K,48K) Blo[48K,80K)

// ---------------- scratch (device globals: allocation-free) ----------------
__device__ float g_inv[(size_t)TT * NH];
__device__ __half g_khi[(size_t)TT * NKV * HD];
__device__ __half g_klo[(size_t)TT * NKV * HD];
__device__ __half g_Posal[(size_t)NSALT * NH * SMAXK];     // single fp16 plane
__device__ __half g_vnT_hi[(size_t)NKV * HD * TT];
__device__ __half g_vnT_lo[(size_t)NKV * HD * TT];
__device__ __half g_vdT_hi[(size_t)NKV * HD * NSALT];
__device__ __half g_vdT_lo[(size_t)NKV * HD * NSALT];
__device__ int   g_idx[NSALT];
__device__ int   g_cu[NSEG + 1];
__device__ int   g_salpos[TT];
__device__ int   g_salst[NSEG];
__device__ int   g_salcnt[NSEG];

// ---------------- helpers ----------------
__device__ __forceinline__ uint32_t smem_to_u32(const void* p) {
    uint32_t a;
    asm("{ .reg .u64 t; cvta.to.shared.u64 t, %1; cvt.u32.u64 %0, t; }" : "=r"(a) : "l"(p));
    return a;
}
__device__ __forceinline__ void ldsm4(uint32_t* r, uint32_t addr) {
    asm volatile("ldmatrix.sync.aligned.m8n8.x4.shared.b16 {%0,%1,%2,%3}, [%4];"
        : "=r"(r[0]), "=r"(r[1]), "=r"(r[2]), "=r"(r[3]) : "r"(addr));
}
__device__ __forceinline__ void mma16816(float* c, const uint32_t* a, uint32_t b0, uint32_t b1) {
    asm volatile("mma.sync.aligned.m16n8k16.row.col.f32.f16.f16.f32 "
        "{%0,%1,%2,%3}, {%4,%5,%6,%7}, {%8,%9}, {%0,%1,%2,%3};"
        : "+f"(c[0]), "+f"(c[1]), "+f"(c[2]), "+f"(c[3])
        : "r"(a[0]), "r"(a[1]), "r"(a[2]), "r"(a[3]), "r"(b0), "r"(b1));
}
__device__ __forceinline__ void cpa16(uint32_t dst, const void* src, bool valid) {
    int sz = valid ? 16 : 0;
    asm volatile("cp.async.cg.shared.global [%0], [%1], 16, %2;"
        :: "r"(dst), "l"(src), "r"(sz) : "memory");
}
#define CP_COMMIT() asm volatile("cp.async.commit_group;" ::: "memory")
#define CP_WAIT0()  asm volatile("cp.async.wait_group 0;" ::: "memory")
#define CP_WAIT1()  asm volatile("cp.async.wait_group 1;" ::: "memory")

__device__ __forceinline__ float fexp2(float x) {
    float r;
    asm("ex2.approx.f32 %0, %1;" : "=f"(r) : "f"(x));
    return r;
}
__device__ __forceinline__ void hf_split(float x, __half& h, __half& l) {
    h = __float2half_rn(x);
    l = __float2half_rn(x - __half2float(h));
}

// QK tile: 64(m)x64(n)x128(k), 2-pass fp16. A single plane @0; B hi@bOff, lo@bOff+16K.
__device__ __forceinline__ void hmma_qk2(uint32_t sb, uint32_t bOff, float acc[2][2][4],
                                         int wid, int lane) {
    const int wm = wid >> 2, wn = wid & 3;
    uint32_t a_ad[2], a_rx[2];
#pragma unroll
    for (int mf = 0; mf < 2; mf++) {
        int row = wm * 32 + mf * 16 + (lane & 15);
        a_ad[mf] = sb + row * 256;
        a_rx[mf] = ((uint32_t)(row & 7)) << 4;
    }
    const int achunk = (lane >> 4);
    int n = wn * 16 + (lane & 7) + ((lane >> 4) << 3);
    uint32_t b_ad = sb + bOff + n * 256;
    uint32_t b_rx = ((uint32_t)(n & 7)) << 4;
    const int bchunk = (lane >> 3) & 1;
#pragma unroll
    for (int ks = 0; ks < 8; ks++) {
        uint32_t ah[2][4];
#pragma unroll
        for (int mf = 0; mf < 2; mf++) {
            uint32_t coff = (((uint32_t)(ks * 2 + achunk)) << 4) ^ a_rx[mf];
            ldsm4(ah[mf], a_ad[mf] + coff);
        }
        uint32_t bh[4], bl[4];
        {
            uint32_t coff = (((uint32_t)(ks * 2 + bchunk)) << 4) ^ b_rx;
            ldsm4(bh, b_ad + coff);
            ldsm4(bl, b_ad + 16384u + coff);
        }
#pragma unroll
        for (int mf = 0; mf < 2; mf++)
#pragma unroll
            for (int nf = 0; nf < 2; nf++) {
                int sel = nf * 2;
                mma16816(acc[mf][nf], ah[mf], bh[sel], bh[sel + 1]);
                mma16816(acc[mf][nf], ah[mf], bl[sel], bl[sel + 1]);
            }
    }
}

// PV tile: 64(m)x128(n)x128(k), 2-pass. A single plane @aOff; B hi@bOff, lo@bOff+bLoD.
__device__ __forceinline__ void hmma_2p(uint32_t sb, uint32_t aOff, uint32_t bOff, uint32_t bLoD,
                                        float acc[2][4][4], int wid, int lane) {
    const int wm = wid >> 2, wn = wid & 3;
    uint32_t a_ad[2], a_rx[2];
#pragma unroll
    for (int mf = 0; mf < 2; mf++) {
        int row = wm * 32 + mf * 16 + (lane & 15);
        a_ad[mf] = sb + aOff + row * 256;
        a_rx[mf] = ((uint32_t)(row & 7)) << 4;
    }
    const int achunk = (lane >> 4);
    uint32_t b_ad[2], b_rx[2];
#pragma unroll
    for (int bg = 0; bg < 2; bg++) {
        int n = wn * 32 + bg * 16 + (lane & 7) + ((lane >> 4) << 3);
        b_ad[bg] = sb + bOff + n * 256;
        b_rx[bg] = ((uint32_t)(n & 7)) << 4;
    }
    const int bchunk = (lane >> 3) & 1;
#pragma unroll
    for (int ks = 0; ks < 8; ks++) {
        uint32_t ah[2][4];
#pragma unroll
        for (int mf = 0; mf < 2; mf++) {
            uint32_t coff = (((uint32_t)(ks * 2 + achunk)) << 4) ^ a_rx[mf];
            ldsm4(ah[mf], a_ad[mf] + coff);
        }
        uint32_t bh[2][4], bl[2][4];
#pragma unroll
        for (int bg = 0; bg < 2; bg++) {
            uint32_t coff = (((uint32_t)(ks * 2 + bchunk)) << 4) ^ b_rx[bg];
            ldsm4(bh[bg], b_ad[bg] + coff);
            ldsm4(bl[bg], b_ad[bg] + bLoD + coff);
        }
#pragma unroll
        for (int mf = 0; mf < 2; mf++)
#pragma unroll
            for (int nf = 0; nf < 4; nf++) {
                int bg = nf >> 1, sel = (nf & 1) * 2;
                mma16816(acc[mf][nf], ah[mf], bh[bg][sel], bh[bg][sel + 1]);
                mma16816(acc[mf][nf], ah[mf], bl[bg][sel], bl[bg][sel + 1]);
            }
    }
}

// store one P value into swizzled Pstage (single fp16 plane @PSTO)
__device__ __forceinline__ void sts_p(char* dsm, int row, int salcol, float val) {
    uint32_t off = (uint32_t)row * 256 + ((((uint32_t)(salcol >> 3)) ^ (uint32_t)(row & 7)) << 4)
                 + (uint32_t)((2 * salcol) & 15);
    *(__half*)(dsm + PSTO + off) = __float2half_rn(val);
}

// ---------------- K0a: decode indices, segment tables ----------------
__global__ void k_prep(const void* idx_raw, const void* cu_raw) {
    const int* i32 = (const int*)idx_raw;
    const int* c32 = (const int*)cu_raw;
    const bool idx64 = (i32[1] == 0);
    const bool cu64  = (c32[1] == 0);
    const int t = threadIdx.x;

    for (int i = t; i < NSALT; i += 256)
        g_idx[i] = idx64 ? (int)((const long long*)idx_raw)[i] : i32[i];
    if (t <= NSEG)
        g_cu[t] = cu64 ? (int)((const long long*)cu_raw)[t] : c32[t];
    for (int i = t; i < TT; i += 256) g_salpos[i] = -1;
    __syncthreads();
    for (int i = t; i < NSALT; i += 256) g_salpos[g_idx[i]] = i;
    if (t == 0) {
        for (int s = 0; s < NSEG; s++) {
            int a = 0;
            while (a < NSALT && g_idx[a] < g_cu[s]) a++;
            int b = a;
            while (b < NSALT && g_idx[b] < g_cu[s + 1]) b++;
            g_salst[s] = a;
            g_salcnt[s] = b - a;
        }
    }
}

// ---------------- K0b (merged): K cvt || build_vn || build_vd (fp16 hi/lo) ----------------
__global__ void __launch_bounds__(256) k_pre(const float* __restrict__ kk,
                                             const float* __restrict__ v, const float* __restrict__ vc) {
    extern __shared__ float tile[];   // [32][129]
    const int bx = blockIdx.x;
    const int tid = threadIdx.x;

    if (bx < CVT_BLKS) {
        int i = bx * 256 + tid;
        float4 x = ((const float4*)kk)[i];
        __half hh[4], ll[4];
        hf_split(x.x, hh[0], ll[0]); hf_split(x.y, hh[1], ll[1]);
        hf_split(x.z, hh[2], ll[2]); hf_split(x.w, hh[3], ll[3]);
        *(uint2*)(g_khi + 4 * (size_t)i) = *(uint2*)hh;
        *(uint2*)(g_klo + 4 * (size_t)i) = *(uint2*)ll;
        return;
    }

    if (bx < CVT_BLKS + VN_BLKS) {
        int t2 = bx - CVT_BLKS;
        int kc = t2 >> 3, g = t2 & 7;
#pragma unroll
        for (int it = 0; it < 4; it++) {
            int fi = tid + it * 256;
            int key = fi >> 5, c4 = fi & 31;
            int gk = kc * 32 + key;
            int sp = g_salpos[gk];
            const float* src = (sp >= 0) ? v + ((size_t)sp * NKV + g) * HD + c4 * 4
                                         : vc + ((size_t)gk * NKV + g) * HD + c4 * 4;
            float4 x = *(const float4*)src;
            float* tr = tile + key * 129 + c4 * 4;
            tr[0] = x.x; tr[1] = x.y; tr[2] = x.z; tr[3] = x.w;
        }
        __syncthreads();
#pragma unroll
        for (int it = 0; it < 8; it++) {
            int wi = tid + it * 256;
            int d = wi >> 4, kp = wi & 15;
            float v0 = tile[(2 * kp) * 129 + d], v1 = tile[(2 * kp + 1) * 129 + d];
            __half h0, l0, h1, l1;
            hf_split(v0, h0, l0); hf_split(v1, h1, l1);
            __half2 ph; ph.x = h0; ph.y = h1;
            __half2 pl; pl.x = l0; pl.y = l1;
            size_t dst = ((size_t)g * HD + d) * TT + kc * 32 + 2 * kp;
            *(__half2*)(g_vnT_hi + dst) = ph;
            *(__half2*)(g_vnT_lo + dst) = pl;
        }
        return;
    }

    {
        int t2 = bx - CVT_BLKS - VN_BLKS;
        int kc = t2 >> 3, g = t2 & 7;
#pragma unroll
        for (int it = 0; it < 4; it++) {
            int fi = tid + it * 256;
            int sidx = fi >> 5, c4 = fi & 31;
            int sal = kc * 32 + sidx;
            const float* pv = v  + ((size_t)sal * NKV + g) * HD + c4 * 4;
            const float* pc = vc + ((size_t)g_idx[sal] * NKV + g) * HD + c4 * 4;
            float4 a = *(const float4*)pv;
            float4 b = *(const float4*)pc;
            float* tr = tile + sidx * 129 + c4 * 4;
            tr[0] = a.x - b.x; tr[1] = a.y - b.y; tr[2] = a.z - b.z; tr[3] = a.w - b.w;
        }
        __syncthreads();
#pragma unroll
        for (int it = 0; it < 8; it++) {
            int wi = tid + it * 256;
            int d = wi >> 4, kp = wi & 15;
            float v0 = tile[(2 * kp) * 129 + d], v1 = tile[(2 * kp + 1) * 129 + d];
            __half h0, l0, h1, l1;
            hf_split(v0, h0, l0); hf_split(v1, h1, l1);
            __half2 ph; ph.x = h0; ph.y = h1;
            __half2 pl; pl.x = l0; pl.y = l1;
            size_t dst = ((size_t)g * HD + d) * NSALT + kc * 32 + 2 * kp;
            *(__half2*)(g_vdT_hi + dst) = ph;
            *(__half2*)(g_vdT_lo + dst) = pl;
        }
    }
}

// ---------------- K1: fused QK^T + exp + rowsum + delta-PV (fp16, double-buffered K) ----------------
__device__ __forceinline__ void qk_loadK(uint32_t sb, uint32_t buf, int tid, int nt, int s0, int L, int g) {
#pragma unroll
    for (int it = 0; it < 4; it++) {
        int idx = tid + it * 256;
        int r = idx >> 4, ch = idx & 15;
        uint32_t d = (uint32_t)(r * 256) + (((uint32_t)(ch ^ (r & 7))) << 4);
        int jg = nt * 64 + r;
        bool v = jg < L;
        size_t o = v ? (((size_t)(s0 + jg) * NKV + g) * HD + ch * 8) : 0;
        cpa16(sb + buf + d, g_khi + o, v);
        cpa16(sb + buf + 16384u + d, g_klo + o, v);
    }
}

__global__ void __launch_bounds__(256, 2) k_qk(const float* __restrict__ qf,
                                               const float* __restrict__ cc, float* __restrict__ outc) {
    extern __shared__ char dsm[];
    __shared__ int s_sp[SMAXK];
    __shared__ float s_red[64 * 4];
    const int sg = blockIdx.y;
    const int s = sg >> 3, g = sg & 7;
    const int s0 = g_cu[s];
    const int L = g_cu[s + 1] - s0;
    const int mBase = blockIdx.x * 64;
    if (mBase >= 4 * L) return;
    const int salst = g_salst[s], salcnt = g_salcnt[s];

    const int tid = threadIdx.x, wid = tid >> 5, lane = tid & 31;
    const int wm = wid >> 2, wn = wid & 3;
    const uint32_t sb = smem_to_u32(dsm);

    // prime K tiles 0,1
    qk_loadK(sb, KB0, tid, 0, s0, L, g);
    CP_COMMIT();
    qk_loadK(sb, KB1, tid, 1, s0, L, g);
    CP_COMMIT();

    for (int j = tid; j < L; j += 256) {
        int sp = g_salpos[s0 + j];
        s_sp[j] = sp >= 0 ? sp - salst : -1;
    }

    // zero Pstage (16KB)
    {
        uint4 z = make_uint4(0, 0, 0, 0);
#pragma unroll
        for (int it = 0; it < 4; it++)
            *(uint4*)(dsm + PSTO + (size_t)(tid + it * 256) * 16) = z;
    }

    // Q tile: fp32 -> fp16(q*SCALE_L2E) single plane, swizzled STS
#pragma unroll
    for (int it = 0; it < 4; it++) {
        int idx = tid + it * 256;
        int r = idx >> 4, ch = idx & 15;
        uint32_t d = (uint32_t)(r * 256) + (((uint32_t)(ch ^ (r & 7))) << 4);
        int mm = mBase + r, il = mm >> 2, hh = mm & 3;
        __half2 h2[4];
        if (il < L) {
            const float4* src = (const float4*)(qf + ((size_t)(s0 + il) * NH + 4 * g + hh) * HD + ch * 8);
            float4 x0 = src[0], x1 = src[1];
            h2[0] = __floats2half2_rn(x0.x * SCALE_L2E, x0.y * SCALE_L2E);
            h2[1] = __floats2half2_rn(x0.z * SCALE_L2E, x0.w * SCALE_L2E);
            h2[2] = __floats2half2_rn(x1.x * SCALE_L2E, x1.y * SCALE_L2E);
            h2[3] = __floats2half2_rn(x1.z * SCALE_L2E, x1.w * SCALE_L2E);
        } else {
            h2[0] = h2[1] = h2[2] = h2[3] = __floats2half2_rn(0.f, 0.f);
        }
        *(uint4*)(dsm + d) = *(uint4*)h2;
    }

    // per-row metadata (Posal base for salient rows)
    ll pb0[2], pb1[2];
    bool ok0[2], ok1[2];
    int rb[2];
#pragma unroll
    for (int mf = 0; mf < 2; mf++) {
        rb[mf] = wm * 32 + mf * 16 + (lane >> 2);
        int mr0 = mBase + rb[mf];
        int mr1 = mr0 + 8;
        int il0 = mr0 >> 2, h0 = mr0 & 3;
        int il1 = mr1 >> 2, h1 = mr1 & 3;
        ok0[mf] = il0 < L; ok1[mf] = il1 < L;
        int sp0 = ok0[mf] ? g_salpos[s0 + il0] : -1;
        int sp1 = ok1[mf] ? g_salpos[s0 + il1] : -1;
        pb0[mf] = sp0 >= 0 ? ((ll)sp0 * NH + 4 * g + h0) * SMAXK : -1;
        pb1[mf] = sp1 >= 0 ? ((ll)sp1 * NH + 4 * g + h1) * SMAXK : -1;
    }

    float rs0[2] = {0.f, 0.f}, rs1[2] = {0.f, 0.f};

    for (int nt = 0; nt < 8; nt++) {
        CP_WAIT1();
        __syncthreads();

        float acc[2][2][4];
#pragma unroll
        for (int a = 0; a < 2; a++)
#pragma unroll
            for (int b = 0; b < 2; b++)
#pragma unroll
                for (int c = 0; c < 4; c++) acc[a][b][c] = 0.f;

        uint32_t buf = (nt & 1) ? KB1 : KB0;
        hmma_qk2(sb, buf, acc, wid, lane);
        __syncthreads();   // this K buffer now dead
        if (nt < 6) {
            qk_loadK(sb, buf, tid, nt + 2, s0, L, g);
            CP_COMMIT();
        } else if (nt == 6) {
            // vd_hi -> KB0 region (32KB plane)
#pragma unroll
            for (int it = 0; it < 8; it++) {
                int idx = tid + it * 256;
                int r = idx >> 4, ch = idx & 15;
                uint32_t d = (uint32_t)(r * 256) + (((uint32_t)(ch ^ (r & 7))) << 4);
                bool vb = (ch * 8 < salcnt);
                size_t ib = vb ? (((size_t)(g * HD + r)) * NSALT + salst + ch * 8) : 0;
                cpa16(sb + KB0 + d, g_vdT_hi + ib, vb);
            }
            CP_COMMIT();
        } else {
            // vd_lo -> KB1 region
#pragma unroll
            for (int it = 0; it < 8; it++) {
                int idx = tid + it * 256;
                int r = idx >> 4, ch = idx & 15;
                uint32_t d = (uint32_t)(r * 256) + (((uint32_t)(ch ^ (r & 7))) << 4);
                bool vb = (ch * 8 < salcnt);
                size_t ib = vb ? (((size_t)(g * HD + r)) * NSALT + salst + ch * 8) : 0;
                cpa16(sb + KB1 + d, g_vdT_lo + ib, vb);
            }
            CP_COMMIT();
        }

        // epilogue: exp (scale pre-folded), rowsum, Pstage STS, Posal STG (single fp16)
#pragma unroll
        for (int nf = 0; nf < 2; nf++) {
            int col = nt * 64 + wn * 16 + nf * 8 + (lane & 3) * 2;
            bool c0 = col < L, c1 = col + 1 < L;
            int spa = c0 ? s_sp[col] : -1;
            int spb = c1 ? s_sp[col + 1] : -1;
#pragma unroll
            for (int mf = 0; mf < 2; mf++) {
                float* c = acc[mf][nf];
                float e0 = (ok0[mf] && c0) ? fexp2(c[0]) : 0.f;
                float e1 = (ok0[mf] && c1) ? fexp2(c[1]) : 0.f;
                float e2 = (ok1[mf] && c0) ? fexp2(c[2]) : 0.f;
                float e3 = (ok1[mf] && c1) ? fexp2(c[3]) : 0.f;
                rs0[mf] += e0 + e1;
                rs1[mf] += e2 + e3;
                int r0 = rb[mf], r1 = r0 + 8;
                if (spa >= 0) {
                    if (ok0[mf]) sts_p(dsm, r0, spa, e0);
                    if (ok1[mf]) sts_p(dsm, r1, spa, e2);
                }
                if (spb >= 0) {
                    if (ok0[mf]) sts_p(dsm, r0, spb, e1);
                    if (ok1[mf]) sts_p(dsm, r1, spb, e3);
                }
                if (pb0[mf] >= 0 && c0)
                    *(__half2*)(g_Posal + pb0[mf] + col) = __floats2half2_rn(e0, e1);
                if (pb1[mf] >= 0 && c0)
                    *(__half2*)(g_Posal + pb1[mf] + col) = __floats2half2_rn(e2, e3);
            }
        }
    }

    // rowsum reduction across n-warps
#pragma unroll
    for (int mf = 0; mf < 2; mf++) {
        rs0[mf] += __shfl_xor_sync(0xffffffffu, rs0[mf], 1);
        rs0[mf] += __shfl_xor_sync(0xffffffffu, rs0[mf], 2);
        rs1[mf] += __shfl_xor_sync(0xffffffffu, rs1[mf], 1);
        rs1[mf] += __shfl_xor_sync(0xffffffffu, rs1[mf], 2);
    }
    if ((lane & 3) == 0) {
#pragma unroll
        for (int mf = 0; mf < 2; mf++) {
            s_red[rb[mf] * 4 + wn] = rs0[mf];
            s_red[(rb[mf] + 8) * 4 + wn] = rs1[mf];
        }
    }
    CP_WAIT0();           // vd planes in
    __syncthreads();

    // g_inv for osal
    if (tid < 64) {
        int mm = mBase + tid, il = mm >> 2, h = mm & 3;
        if (il < L) {
            float s4 = s_red[tid * 4] + s_red[tid * 4 + 1] + s_red[tid * 4 + 2] + s_red[tid * 4 + 3];
            g_inv[(size_t)(s0 + il) * NH + 4 * g + h] = 1.f / s4;
        }
    }

    // delta PV: Pstage (A, single) @ vdT (B hi@KB0, lo@KB1), 2-pass
    float pv[2][4][4];
#pragma unroll
    for (int a = 0; a < 2; a++)
#pragma unroll
        for (int b = 0; b < 4; b++)
#pragma unroll
            for (int c = 0; c < 4; c++) pv[a][b][c] = 0.f;
    hmma_2p(sb, PSTO, KB0, KB1 - KB0, pv, wid, lane);

    // output: non-salient rows only (salient rows overwritten by k_pv)
#pragma unroll
    for (int mf = 0; mf < 2; mf++) {
        int r0 = rb[mf], r1 = r0 + 8;
        int mr0 = mBase + r0, mr1 = mBase + r1;
        int il0 = mr0 >> 2, h0 = mr0 & 3;
        int il1 = mr1 >> 2, h1 = mr1 & 3;
        bool w0 = (il0 < L) && (g_salpos[s0 + il0] < 0);
        bool w1 = (il1 < L) && (g_salpos[s0 + il1] < 0);
        float inv0 = 0.f, inv1 = 0.f;
        if (w0) inv0 = 1.f / (s_red[r0 * 4] + s_red[r0 * 4 + 1] + s_red[r0 * 4 + 2] + s_red[r0 * 4 + 3]);
        if (w1) inv1 = 1.f / (s_red[r1 * 4] + s_red[r1 * 4 + 1] + s_red[r1 * 4 + 2] + s_red[r1 * 4 + 3]);
        size_t id0 = (size_t)(s0 + il0) * NH + 4 * g + h0;
        size_t id1 = (size_t)(s0 + il1) * NH + 4 * g + h1;
#pragma unroll
        for (int nf = 0; nf < 4; nf++) {
            int dcol = wn * 32 + nf * 8 + (lane & 3) * 2;
            float* c = pv[mf][nf];
            if (w0) {
                size_t ob = id0 * HD + dcol;
                float2 cv = *(const float2*)(cc + ob);
                *(float2*)(outc + ob) = make_float2(cv.x + inv0 * c[0], cv.y + inv0 * c[1]);
            }
            if (w1) {
                size_t ob = id1 * HD + dcol;
                float2 cv = *(const float2*)(cc + ob);
                *(float2*)(outc + ob) = make_float2(cv.x + inv1 * c[2], cv.y + inv1 * c[3]);
            }
        }
    }
}

// ---------------- K2: osal: salient rows out = inv * (Posal @ vnT), 2-pass ----------------
__global__ void __launch_bounds__(256, 2) k_pv(float* __restrict__ outc) {
    extern __shared__ char dsm[];
    const int sg = blockIdx.y;
    const int s = sg >> 3, g = sg & 7;
    const int s0 = g_cu[s];
    const int L = g_cu[s + 1] - s0;
    const int salst = g_salst[s], salcnt = g_salcnt[s];

    const int tid = threadIdx.x, wid = tid >> 5, lane = tid & 31;
    const int wm = wid >> 2, wn = wid & 3;
    const uint32_t sb = smem_to_u32(dsm);

    const int mBase = blockIdx.x * 64;
    if (mBase >= 4 * salcnt) return;

    float acc[2][4][4];
#pragma unroll
    for (int a = 0; a < 2; a++)
#pragma unroll
        for (int b = 0; b < 4; b++)
#pragma unroll
            for (int c = 0; c < 4; c++) acc[a][b][c] = 0.f;

    for (int kc = 0; kc * 128 < L; kc++) {
#pragma unroll
        for (int it = 0; it < 4; it++) {
            int idx = tid + it * 256;
            int r = idx >> 4, ch = idx & 15;
            uint32_t d = (uint32_t)(r * 256) + (((uint32_t)(ch ^ (r & 7))) << 4);
            int m = mBase + r, saloc = m >> 2, hh = m & 3;
            int kk = kc * 128 + ch * 8;
            bool va = (saloc < salcnt) && (kk < L);
            size_t ia = va ? (((size_t)(salst + saloc) * NH + 4 * g + hh) * SMAXK + kk) : 0;
            cpa16(sb + d, g_Posal + ia, va);
        }
#pragma unroll
        for (int it = 0; it < 8; it++) {
            int idx = tid + it * 256;
            int r = idx >> 4, ch = idx & 15;
            uint32_t d = (uint32_t)(r * 256) + (((uint32_t)(ch ^ (r & 7))) << 4);
            int kk = kc * 128 + ch * 8;
            bool vb = (kk < L);
            size_t ib = vb ? (((size_t)(g * HD + r)) * TT + s0 + kk) : 0;
            cpa16(sb + 16384u + d, g_vnT_hi + ib, vb);
            cpa16(sb + 49152u + d, g_vnT_lo + ib, vb);
        }
        CP_COMMIT();
        CP_WAIT0();
        __syncthreads();
        hmma_2p(sb, 0u, 16384u, 32768u, acc, wid, lane);
        __syncthreads();
    }

#pragma unroll
    for (int mf = 0; mf < 2; mf++) {
        int mr0 = mBase + wm * 32 + mf * 16 + (lane >> 2);
        int mr1 = mr0 + 8;
        int sa0 = mr0 >> 2, h0 = mr0 & 3;
        int sa1 = mr1 >> 2, h1 = mr1 & 3;
        bool ok0 = sa0 < salcnt, ok1 = sa1 < salcnt;
        size_t id0 = 0, id1 = 0;
        float inv0 = 0.f, inv1 = 0.f;
        if (ok0) { id0 = (size_t)g_idx[salst + sa0] * NH + 4 * g + h0; inv0 = g_inv[id0]; }
        if (ok1) { id1 = (size_t)g_idx[salst + sa1] * NH + 4 * g + h1; inv1 = g_inv[id1]; }
#pragma unroll
        for (int nf = 0; nf < 4; nf++) {
            int dcol = wn * 32 + nf * 8 + (lane & 3) * 2;
            float* c = acc[mf][nf];
            if (ok0) *(float2*)(outc + id0 * HD + dcol) = make_float2(inv0 * c[0], inv0 * c[1]);
            if (ok1) *(float2*)(outc + id1 * HD + dcol) = make_float2(inv1 * c[2], inv1 * c[3]);
        }
    }
}

// ---------------- K3: per-row cosine similarity ----------------
__global__ void __launch_bounds__(512) k_cos(const float* __restrict__ cc, const float* __restrict__ outc,
                                             float* __restrict__ cosv) {
    const int tid = threadIdx.x, wid = tid >> 5, lane = tid & 31;
    size_t base = (size_t)blockIdx.x * (NH * HD);
    const float4* a4 = (const float4*)(cc + base);
    const float4* b4 = (const float4*)(outc + base);
    float ab = 0.f, aa = 0.f, bb = 0.f;
#pragma unroll
    for (int j = 0; j < 2; j++) {
        float4 x = a4[tid + j * 512], y = b4[tid + j * 512];
        ab += x.x * y.x + x.y * y.y + x.z * y.z + x.w * y.w;
        aa += x.x * x.x + x.y * x.y + x.z * x.z + x.w * x.w;
        bb += y.x * y.x + y.y * y.y + y.z * y.z + y.w * y.w;
    }
#pragma unroll
    for (int o = 16; o; o >>= 1) {
        ab += __shfl_xor_sync(0xffffffffu, ab, o);
        aa += __shfl_xor_sync(0xffffffffu, aa, o);
        bb += __shfl_xor_sync(0xffffffffu, bb, o);
    }
    __shared__ float sh[3][16];
    if (lane == 0) { sh[0][wid] = ab; sh[1][wid] = aa; sh[2][wid] = bb; }
    __syncthreads();
    if (tid < 32) {
        float a2 = (tid < 16) ? sh[0][tid] : 0.f;
        float b2 = (tid < 16) ? sh[1][tid] : 0.f;
        float c2 = (tid < 16) ? sh[2][tid] : 0.f;
#pragma unroll
        for (int o = 8; o; o >>= 1) {
            a2 += __shfl_xor_sync(0xffffffffu, a2, o);
            b2 += __shfl_xor_sync(0xffffffffu, b2, o);
            c2 += __shfl_xor_sync(0xffffffffu, c2, o);
        }
        if (tid == 0)
            cosv[blockIdx.x] = a2 / (sqrtf(b2) * sqrtf(c2) + 1e-8f);
    }
}

// ---------------- launch ----------------
extern "C" void kernel_launch(void* const* d_in, const int* in_sizes, int n_in,
                              void* d_out, int out_size) {
    const float* q       = (const float*)d_in[0];
    const float* k       = (const float*)d_in[1];
    const float* v       = (const float*)d_in[2];
    const float* v_cache = (const float*)d_in[3];
    const float* c_cache = (const float*)d_in[4];
    const void*  idx     = d_in[5];
    const void*  cu      = d_in[6];

    float* outc = (float*)d_out;
    float* cosv = outc + (size_t)(out_size - TT);

    cudaFuncSetAttribute(k_qk,  cudaFuncAttributeMaxDynamicSharedMemorySize, 98304);
    cudaFuncSetAttribute(k_pv,  cudaFuncAttributeMaxDynamicSharedMemorySize, 98304);
    cudaFuncSetAttribute(k_pre, cudaFuncAttributeMaxDynamicSharedMemorySize, 16512);

    k_prep<<<1, 256>>>(idx, cu);
    k_pre<<<CVT_BLKS + VN_BLKS + VD_BLKS, 256, 16512>>>(k, v, v_cache);
    k_qk<<<dim3(32, 32), 256, 98304>>>(q, c_cache, outc);
    k_pv<<<dim3(8, 32), 256, 98304>>>(outc);
    k_cos<<<TT, 512>>>(c_cache, outc, cosv);
}

// round 13
// speedup vs baseline: 1.6328x; 1.1479x over previous
#include <cuda_runtime.h>
#include <cuda_fp16.h>
#include <math.h>
#include <stdint.h>

typedef unsigned long long ull;
typedef long long ll;

#define TT    2048
#define NH    32
#define NKV   8
#define HD    128
#define NSALT 512
#define NSEG  4
#define SMAXK 512
#define SCALE_L2E 0.12751742788f   /* (1/sqrt(128)) * log2(e), folded into Q */

#define CVT_BLKS 2048
#define VN_BLKS  512
#define VD_BLKS  128

// k_qk smem (96KB): Q[0,16K) KB0[16K,48K) KB1[48K,80K) Pst[80K,96K)
// PV phase: vdT single plane -> KB0
#define QOFF 0u
#define KB0  16384u
#define KB1  49152u
#define PSTO 81920u
// k_pv smem (96KB): A0[0,16K) B0[16K,48K) A1[48K,64K) B1[64K,96K)
#define PV_A0 0u
#define PV_B0 16384u
#define PV_A1 49152u
#define PV_B1 65536u

// ---------------- scratch (device globals: allocation-free) ----------------
__device__ float g_inv[(size_t)TT * NH];
__device__ __half g_k[(size_t)TT * NKV * HD];
__device__ __half g_Posal[(size_t)NSALT * NH * SMAXK];
__device__ __half g_vnT[(size_t)NKV * HD * TT];
__device__ __half g_vdT[(size_t)NKV * HD * NSALT];
__device__ int   g_idx[NSALT];
__device__ int   g_cu[NSEG + 1];
__device__ int   g_salpos[TT];
__device__ int   g_salst[NSEG];
__device__ int   g_salcnt[NSEG];

// ---------------- helpers ----------------
__device__ __forceinline__ uint32_t smem_to_u32(const void* p) {
    uint32_t a;
    asm("{ .reg .u64 t; cvta.to.shared.u64 t, %1; cvt.u32.u64 %0, t; }" : "=r"(a) : "l"(p));
    return a;
}
__device__ __forceinline__ void ldsm4(uint32_t* r, uint32_t addr) {
    asm volatile("ldmatrix.sync.aligned.m8n8.x4.shared.b16 {%0,%1,%2,%3}, [%4];"
        : "=r"(r[0]), "=r"(r[1]), "=r"(r[2]), "=r"(r[3]) : "r"(addr));
}
__device__ __forceinline__ void mma16816(float* c, const uint32_t* a, uint32_t b0, uint32_t b1) {
    asm volatile("mma.sync.aligned.m16n8k16.row.col.f32.f16.f16.f32 "
        "{%0,%1,%2,%3}, {%4,%5,%6,%7}, {%8,%9}, {%0,%1,%2,%3};"
        : "+f"(c[0]), "+f"(c[1]), "+f"(c[2]), "+f"(c[3])
        : "r"(a[0]), "r"(a[1]), "r"(a[2]), "r"(a[3]), "r"(b0), "r"(b1));
}
__device__ __forceinline__ void cpa16(uint32_t dst, const void* src, bool valid) {
    int sz = valid ? 16 : 0;
    asm volatile("cp.async.cg.shared.global [%0], [%1], 16, %2;"
        :: "r"(dst), "l"(src), "r"(sz) : "memory");
}
#define CP_COMMIT() asm volatile("cp.async.commit_group;" ::: "memory")
#define CP_WAIT0()  asm volatile("cp.async.wait_group 0;" ::: "memory")
#define CP_WAIT1()  asm volatile("cp.async.wait_group 1;" ::: "memory")

__device__ __forceinline__ float fexp2(float x) {
    float r;
    asm("ex2.approx.f32 %0, %1;" : "=f"(r) : "f"(x));
    return r;
}

// 64(m)x128(n)x128(k) 1-pass fp16 HMMA. A single plane @aOff; B single plane @bOff.
// Rows 256B, 16B-chunk XOR swizzle. 8 warps = 2(m) x 4(n). acc[2][4][4].
__device__ __forceinline__ void hmma_1p(uint32_t sb, uint32_t aOff, uint32_t bOff,
                                        float acc[2][4][4], int wid, int lane) {
    const int wm = wid >> 2, wn = wid & 3;
    uint32_t a_ad[2], a_rx[2];
#pragma unroll
    for (int mf = 0; mf < 2; mf++) {
        int row = wm * 32 + mf * 16 + (lane & 15);
        a_ad[mf] = sb + aOff + row * 256;
        a_rx[mf] = ((uint32_t)(row & 7)) << 4;
    }
    const int achunk = (lane >> 4);
    uint32_t b_ad[2], b_rx[2];
#pragma unroll
    for (int bg = 0; bg < 2; bg++) {
        int n = wn * 32 + bg * 16 + (lane & 7) + ((lane >> 4) << 3);
        b_ad[bg] = sb + bOff + n * 256;
        b_rx[bg] = ((uint32_t)(n & 7)) << 4;
    }
    const int bchunk = (lane >> 3) & 1;
#pragma unroll
    for (int ks = 0; ks < 8; ks++) {
        uint32_t ah[2][4];
#pragma unroll
        for (int mf = 0; mf < 2; mf++) {
            uint32_t coff = (((uint32_t)(ks * 2 + achunk)) << 4) ^ a_rx[mf];
            ldsm4(ah[mf], a_ad[mf] + coff);
        }
        uint32_t bh[2][4];
#pragma unroll
        for (int bg = 0; bg < 2; bg++) {
            uint32_t coff = (((uint32_t)(ks * 2 + bchunk)) << 4) ^ b_rx[bg];
            ldsm4(bh[bg], b_ad[bg] + coff);
        }
#pragma unroll
        for (int mf = 0; mf < 2; mf++)
#pragma unroll
            for (int nf = 0; nf < 4; nf++) {
                int bg = nf >> 1, sel = (nf & 1) * 2;
                mma16816(acc[mf][nf], ah[mf], bh[bg][sel], bh[bg][sel + 1]);
            }
    }
}

// store one P value into swizzled Pstage (single fp16 plane @PSTO)
__device__ __forceinline__ void sts_p(char* dsm, int row, int salcol, float val) {
    uint32_t off = (uint32_t)row * 256 + ((((uint32_t)(salcol >> 3)) ^ (uint32_t)(row & 7)) << 4)
                 + (uint32_t)((2 * salcol) & 15);
    *(__half*)(dsm + PSTO + off) = __float2half_rn(val);
}

// ---------------- K0a: decode indices, segment tables ----------------
__global__ void k_prep(const void* idx_raw, const void* cu_raw) {
    const int* i32 = (const int*)idx_raw;
    const int* c32 = (const int*)cu_raw;
    const bool idx64 = (i32[1] == 0);
    const bool cu64  = (c32[1] == 0);
    const int t = threadIdx.x;

    for (int i = t; i < NSALT; i += 256)
        g_idx[i] = idx64 ? (int)((const long long*)idx_raw)[i] : i32[i];
    if (t <= NSEG)
        g_cu[t] = cu64 ? (int)((const long long*)cu_raw)[t] : c32[t];
    for (int i = t; i < TT; i += 256) g_salpos[i] = -1;
    __syncthreads();
    for (int i = t; i < NSALT; i += 256) g_salpos[g_idx[i]] = i;
    if (t == 0) {
        for (int s = 0; s < NSEG; s++) {
            int a = 0;
            while (a < NSALT && g_idx[a] < g_cu[s]) a++;
            int b = a;
            while (b < NSALT && g_idx[b] < g_cu[s + 1]) b++;
            g_salst[s] = a;
            g_salcnt[s] = b - a;
        }
    }
}

// ---------------- K0b (merged): K cvt || build_vn || build_vd (single fp16) ----------------
__global__ void __launch_bounds__(256) k_pre(const float* __restrict__ kk,
                                             const float* __restrict__ v, const float* __restrict__ vc) {
    extern __shared__ float tile[];   // [32][129]
    const int bx = blockIdx.x;
    const int tid = threadIdx.x;

    if (bx < CVT_BLKS) {
        int i = bx * 256 + tid;
        float4 x = ((const float4*)kk)[i];
        __half2 h2[2];
        h2[0] = __floats2half2_rn(x.x, x.y);
        h2[1] = __floats2half2_rn(x.z, x.w);
        *(uint2*)(g_k + 4 * (size_t)i) = *(uint2*)h2;
        return;
    }

    if (bx < CVT_BLKS + VN_BLKS) {
        int t2 = bx - CVT_BLKS;
        int kc = t2 >> 3, g = t2 & 7;
#pragma unroll
        for (int it = 0; it < 4; it++) {
            int fi = tid + it * 256;
            int key = fi >> 5, c4 = fi & 31;
            int gk = kc * 32 + key;
            int sp = g_salpos[gk];
            const float* src = (sp >= 0) ? v + ((size_t)sp * NKV + g) * HD + c4 * 4
                                         : vc + ((size_t)gk * NKV + g) * HD + c4 * 4;
            float4 x = *(const float4*)src;
            float* tr = tile + key * 129 + c4 * 4;
            tr[0] = x.x; tr[1] = x.y; tr[2] = x.z; tr[3] = x.w;
        }
        __syncthreads();
#pragma unroll
        for (int it = 0; it < 8; it++) {
            int wi = tid + it * 256;
            int d = wi >> 4, kp = wi & 15;
            float v0 = tile[(2 * kp) * 129 + d], v1 = tile[(2 * kp + 1) * 129 + d];
            size_t dst = ((size_t)g * HD + d) * TT + kc * 32 + 2 * kp;
            *(__half2*)(g_vnT + dst) = __floats2half2_rn(v0, v1);
        }
        return;
    }

    {
        int t2 = bx - CVT_BLKS - VN_BLKS;
        int kc = t2 >> 3, g = t2 & 7;
#pragma unroll
        for (int it = 0; it < 4; it++) {
            int fi = tid + it * 256;
            int sidx = fi >> 5, c4 = fi & 31;
            int sal = kc * 32 + sidx;
            const float* pv = v  + ((size_t)sal * NKV + g) * HD + c4 * 4;
            const float* pc = vc + ((size_t)g_idx[sal] * NKV + g) * HD + c4 * 4;
            float4 a = *(const float4*)pv;
            float4 b = *(const float4*)pc;
            float* tr = tile + sidx * 129 + c4 * 4;
            tr[0] = a.x - b.x; tr[1] = a.y - b.y; tr[2] = a.z - b.z; tr[3] = a.w - b.w;
        }
        __syncthreads();
#pragma unroll
        for (int it = 0; it < 8; it++) {
            int wi = tid + it * 256;
            int d = wi >> 4, kp = wi & 15;
            float v0 = tile[(2 * kp) * 129 + d], v1 = tile[(2 * kp + 1) * 129 + d];
            size_t dst = ((size_t)g * HD + d) * NSALT + kc * 32 + 2 * kp;
            *(__half2*)(g_vdT + dst) = __floats2half2_rn(v0, v1);
        }
    }
}

// ---------------- K1: fused QK^T + exp + rowsum + delta-PV (1-pass fp16) ----------------
__device__ __forceinline__ void qk_loadK(uint32_t sb, uint32_t buf, int tid, int nt, int s0, int L, int g) {
    // 128 keys x 16 chunks, single plane (32KB)
#pragma unroll
    for (int it = 0; it < 8; it++) {
        int idx = tid + it * 256;
        int r = idx >> 4, ch = idx & 15;
        uint32_t d = (uint32_t)(r * 256) + (((uint32_t)(ch ^ (r & 7))) << 4);
        int jg = nt * 128 + r;
        bool v = jg < L;
        size_t o = v ? (((size_t)(s0 + jg) * NKV + g) * HD + ch * 8) : 0;
        cpa16(sb + buf + d, g_k + o, v);
    }
}

__global__ void __launch_bounds__(256, 2) k_qk(const float* __restrict__ qf,
                                               const float* __restrict__ cc, float* __restrict__ outc) {
    extern __shared__ char dsm[];
    __shared__ int s_sp[SMAXK];
    __shared__ float s_red[64 * 4];
    const int sg = blockIdx.y;
    const int s = sg >> 3, g = sg & 7;
    const int s0 = g_cu[s];
    const int L = g_cu[s + 1] - s0;
    const int mBase = blockIdx.x * 64;
    if (mBase >= 4 * L) return;
    const int salst = g_salst[s], salcnt = g_salcnt[s];

    const int tid = threadIdx.x, wid = tid >> 5, lane = tid & 31;
    const int wm = wid >> 2, wn = wid & 3;
    const uint32_t sb = smem_to_u32(dsm);

    // prime K tiles 0,1 (128 keys each)
    qk_loadK(sb, KB0, tid, 0, s0, L, g);
    CP_COMMIT();
    qk_loadK(sb, KB1, tid, 1, s0, L, g);
    CP_COMMIT();

    for (int j = tid; j < L; j += 256) {
        int sp = g_salpos[s0 + j];
        s_sp[j] = sp >= 0 ? sp - salst : -1;
    }

    // zero Pstage (16KB)
    {
        uint4 z = make_uint4(0, 0, 0, 0);
#pragma unroll
        for (int it = 0; it < 4; it++)
            *(uint4*)(dsm + PSTO + (size_t)(tid + it * 256) * 16) = z;
    }

    // Q tile: fp32 -> fp16(q*SCALE_L2E) single plane, swizzled STS
#pragma unroll
    for (int it = 0; it < 4; it++) {
        int idx = tid + it * 256;
        int r = idx >> 4, ch = idx & 15;
        uint32_t d = (uint32_t)(r * 256) + (((uint32_t)(ch ^ (r & 7))) << 4);
        int mm = mBase + r, il = mm >> 2, hh = mm & 3;
        __half2 h2[4];
        if (il < L) {
            const float4* src = (const float4*)(qf + ((size_t)(s0 + il) * NH + 4 * g + hh) * HD + ch * 8);
            float4 x0 = src[0], x1 = src[1];
            h2[0] = __floats2half2_rn(x0.x * SCALE_L2E, x0.y * SCALE_L2E);
            h2[1] = __floats2half2_rn(x0.z * SCALE_L2E, x0.w * SCALE_L2E);
            h2[2] = __floats2half2_rn(x1.x * SCALE_L2E, x1.y * SCALE_L2E);
            h2[3] = __floats2half2_rn(x1.z * SCALE_L2E, x1.w * SCALE_L2E);
        } else {
            h2[0] = h2[1] = h2[2] = h2[3] = __floats2half2_rn(0.f, 0.f);
        }
        *(uint4*)(dsm + d) = *(uint4*)h2;
    }

    // per-row metadata (Posal base for salient rows)
    ll pb0[2], pb1[2];
    bool ok0[2], ok1[2];
    int rb[2];
#pragma unroll
    for (int mf = 0; mf < 2; mf++) {
        rb[mf] = wm * 32 + mf * 16 + (lane >> 2);
        int mr0 = mBase + rb[mf];
        int mr1 = mr0 + 8;
        int il0 = mr0 >> 2, h0 = mr0 & 3;
        int il1 = mr1 >> 2, h1 = mr1 & 3;
        ok0[mf] = il0 < L; ok1[mf] = il1 < L;
        int sp0 = ok0[mf] ? g_salpos[s0 + il0] : -1;
        int sp1 = ok1[mf] ? g_salpos[s0 + il1] : -1;
        pb0[mf] = sp0 >= 0 ? ((ll)sp0 * NH + 4 * g + h0) * SMAXK : -1;
        pb1[mf] = sp1 >= 0 ? ((ll)sp1 * NH + 4 * g + h1) * SMAXK : -1;
    }

    float rs0[2] = {0.f, 0.f}, rs1[2] = {0.f, 0.f};

    for (int nt = 0; nt < 4; nt++) {
        CP_WAIT1();
        __syncthreads();

        float acc[2][4][4];
#pragma unroll
        for (int a = 0; a < 2; a++)
#pragma unroll
            for (int b = 0; b < 4; b++)
#pragma unroll
                for (int c = 0; c < 4; c++) acc[a][b][c] = 0.f;

        uint32_t buf = (nt & 1) ? KB1 : KB0;
        hmma_1p(sb, QOFF, buf, acc, wid, lane);
        __syncthreads();   // this K buffer now dead
        if (nt < 2) {
            qk_loadK(sb, buf, tid, nt + 2, s0, L, g);
            CP_COMMIT();
        } else if (nt == 2) {
            // vdT single plane -> KB0 ([128 d][128 sal], 32KB)
#pragma unroll
            for (int it = 0; it < 8; it++) {
                int idx = tid + it * 256;
                int r = idx >> 4, ch = idx & 15;
                uint32_t d = (uint32_t)(r * 256) + (((uint32_t)(ch ^ (r & 7))) << 4);
                bool vb = (ch * 8 < salcnt);
                size_t ib = vb ? (((size_t)(g * HD + r)) * NSALT + salst + ch * 8) : 0;
                cpa16(sb + KB0 + d, g_vdT + ib, vb);
            }
            CP_COMMIT();
        }

        // epilogue: exp (scale pre-folded), rowsum, Pstage STS, Posal STG
#pragma unroll
        for (int nf = 0; nf < 4; nf++) {
            int col = nt * 128 + wn * 32 + nf * 8 + (lane & 3) * 2;
            bool c0 = col < L, c1 = col + 1 < L;
            int spa = c0 ? s_sp[col] : -1;
            int spb = c1 ? s_sp[col + 1] : -1;
#pragma unroll
            for (int mf = 0; mf < 2; mf++) {
                float* c = acc[mf][nf];
                float e0 = (ok0[mf] && c0) ? fexp2(c[0]) : 0.f;
                float e1 = (ok0[mf] && c1) ? fexp2(c[1]) : 0.f;
                float e2 = (ok1[mf] && c0) ? fexp2(c[2]) : 0.f;
                float e3 = (ok1[mf] && c1) ? fexp2(c[3]) : 0.f;
                rs0[mf] += e0 + e1;
                rs1[mf] += e2 + e3;
                int r0 = rb[mf], r1 = r0 + 8;
                if (spa >= 0) {
                    if (ok0[mf]) sts_p(dsm, r0, spa, e0);
                    if (ok1[mf]) sts_p(dsm, r1, spa, e2);
                }
                if (spb >= 0) {
                    if (ok0[mf]) sts_p(dsm, r0, spb, e1);
                    if (ok1[mf]) sts_p(dsm, r1, spb, e3);
                }
                if (pb0[mf] >= 0 && c0)
                    *(__half2*)(g_Posal + pb0[mf] + col) = __floats2half2_rn(e0, e1);
                if (pb1[mf] >= 0 && c0)
                    *(__half2*)(g_Posal + pb1[mf] + col) = __floats2half2_rn(e2, e3);
            }
        }
    }

    // rowsum reduction across n-warps
#pragma unroll
    for (int mf = 0; mf < 2; mf++) {
        rs0[mf] += __shfl_xor_sync(0xffffffffu, rs0[mf], 1);
        rs0[mf] += __shfl_xor_sync(0xffffffffu, rs0[mf], 2);
        rs1[mf] += __shfl_xor_sync(0xffffffffu, rs1[mf], 1);
        rs1[mf] += __shfl_xor_sync(0xffffffffu, rs1[mf], 2);
    }
    if ((lane & 3) == 0) {
#pragma unroll
        for (int mf = 0; mf < 2; mf++) {
            s_red[rb[mf] * 4 + wn] = rs0[mf];
            s_red[(rb[mf] + 8) * 4 + wn] = rs1[mf];
        }
    }
    CP_WAIT0();           // vdT in
    __syncthreads();

    // g_inv for osal
    if (tid < 64) {
        int mm = mBase + tid, il = mm >> 2, h = mm & 3;
        if (il < L) {
            float s4 = s_red[tid * 4] + s_red[tid * 4 + 1] + s_red[tid * 4 + 2] + s_red[tid * 4 + 3];
            g_inv[(size_t)(s0 + il) * NH + 4 * g + h] = 1.f / s4;
        }
    }

    // delta PV: Pstage (A) @ vdT (B @KB0), 1-pass
    float pv[2][4][4];
#pragma unroll
    for (int a = 0; a < 2; a++)
#pragma unroll
        for (int b = 0; b < 4; b++)
#pragma unroll
            for (int c = 0; c < 4; c++) pv[a][b][c] = 0.f;
    hmma_1p(sb, PSTO, KB0, pv, wid, lane);

    // output: non-salient rows only (salient rows overwritten by k_pv)
#pragma unroll
    for (int mf = 0; mf < 2; mf++) {
        int r0 = rb[mf], r1 = r0 + 8;
        int mr0 = mBase + r0, mr1 = mBase + r1;
        int il0 = mr0 >> 2, h0 = mr0 & 3;
        int il1 = mr1 >> 2, h1 = mr1 & 3;
        bool w0 = (il0 < L) && (g_salpos[s0 + il0] < 0);
        bool w1 = (il1 < L) && (g_salpos[s0 + il1] < 0);
        float inv0 = 0.f, inv1 = 0.f;
        if (w0) inv0 = 1.f / (s_red[r0 * 4] + s_red[r0 * 4 + 1] + s_red[r0 * 4 + 2] + s_red[r0 * 4 + 3]);
        if (w1) inv1 = 1.f / (s_red[r1 * 4] + s_red[r1 * 4 + 1] + s_red[r1 * 4 + 2] + s_red[r1 * 4 + 3]);
        size_t id0 = (size_t)(s0 + il0) * NH + 4 * g + h0;
        size_t id1 = (size_t)(s0 + il1) * NH + 4 * g + h1;
#pragma unroll
        for (int nf = 0; nf < 4; nf++) {
            int dcol = wn * 32 + nf * 8 + (lane & 3) * 2;
            float* c = pv[mf][nf];
            if (w0) {
                size_t ob = id0 * HD + dcol;
                float2 cv = *(const float2*)(cc + ob);
                *(float2*)(outc + ob) = make_float2(cv.x + inv0 * c[0], cv.y + inv0 * c[1]);
            }
            if (w1) {
                size_t ob = id1 * HD + dcol;
                float2 cv = *(const float2*)(cc + ob);
                *(float2*)(outc + ob) = make_float2(cv.x + inv1 * c[2], cv.y + inv1 * c[3]);
            }
        }
    }
}

// ---------------- K2: osal: salient rows out = inv * (Posal @ vnT), 1-pass, double-buffered ----------------
__device__ __forceinline__ void pv_loadA(uint32_t sb, uint32_t buf, int tid, int kc,
                                         int mBase, int salst, int salcnt, int L) {
#pragma unroll
    for (int it = 0; it < 4; it++) {
        int idx = tid + it * 256;
        int r = idx >> 4, ch = idx & 15;
        uint32_t d = (uint32_t)(r * 256) + (((uint32_t)(ch ^ (r & 7))) << 4);
        int m = mBase + r, saloc = m >> 2, hh = m & 3;
        int kk = kc * 128 + ch * 8;
        bool va = (saloc < salcnt) && (kk < L);
        size_t ia = va ? (((size_t)(salst + saloc) * NH + hh) * SMAXK + kk) : 0;  // hh adjusted below
        (void)ia;
        // note: head index needs g; handled by caller passing adjusted base — see pv_loadA2
    }
}

__global__ void __launch_bounds__(256, 2) k_pv(float* __restrict__ outc) {
    extern __shared__ char dsm[];
    const int sg = blockIdx.y;
    const int s = sg >> 3, g = sg & 7;
    const int s0 = g_cu[s];
    const int L = g_cu[s + 1] - s0;
    const int salst = g_salst[s], salcnt = g_salcnt[s];

    const int tid = threadIdx.x, wid = tid >> 5, lane = tid & 31;
    const int wm = wid >> 2, wn = wid & 3;
    const uint32_t sb = smem_to_u32(dsm);

    const int mBase = blockIdx.x * 64;
    if (mBase >= 4 * salcnt) return;

    // loader lambdas (A: 64 rows Posal, B: 128 d-rows vnT)
    auto loadA = [&](uint32_t buf, int kc) {
#pragma unroll
        for (int it = 0; it < 4; it++) {
            int idx = tid + it * 256;
            int r = idx >> 4, ch = idx & 15;
            uint32_t d = (uint32_t)(r * 256) + (((uint32_t)(ch ^ (r & 7))) << 4);
            int m = mBase + r, saloc = m >> 2, hh = m & 3;
            int kk = kc * 128 + ch * 8;
            bool va = (saloc < salcnt) && (kk < L);
            size_t ia = va ? (((size_t)(salst + saloc) * NH + 4 * g + hh) * SMAXK + kk) : 0;
            cpa16(sb + buf + d, g_Posal + ia, va);
        }
    };
    auto loadB = [&](uint32_t buf, int kc) {
#pragma unroll
        for (int it = 0; it < 8; it++) {
            int idx = tid + it * 256;
            int r = idx >> 4, ch = idx & 15;
            uint32_t d = (uint32_t)(r * 256) + (((uint32_t)(ch ^ (r & 7))) << 4);
            int kk = kc * 128 + ch * 8;
            bool vb = (kk < L);
            size_t ib = vb ? (((size_t)(g * HD + r)) * TT + s0 + kk) : 0;
            cpa16(sb + buf + d, g_vnT + ib, vb);
        }
    };

    const int nkc = (L + 127) / 128;
    loadA(PV_A0, 0); loadB(PV_B0, 0);
    CP_COMMIT();
    if (nkc > 1) { loadA(PV_A1, 1); loadB(PV_B1, 1); }
    CP_COMMIT();

    float acc[2][4][4];
#pragma unroll
    for (int a = 0; a < 2; a++)
#pragma unroll
        for (int b = 0; b < 4; b++)
#pragma unroll
            for (int c = 0; c < 4; c++) acc[a][b][c] = 0.f;

    for (int kc = 0; kc < nkc; kc++) {
        if (kc == nkc - 1) { CP_WAIT0(); } else { CP_WAIT1(); }
        __syncthreads();
        uint32_t aB = (kc & 1) ? PV_A1 : PV_A0;
        uint32_t bB = (kc & 1) ? PV_B1 : PV_B0;
        hmma_1p(sb, aB, bB, acc, wid, lane);
        __syncthreads();
        if (kc + 2 < nkc) {
            loadA(aB, kc + 2); loadB(bB, kc + 2);
            CP_COMMIT();
        }
    }

#pragma unroll
    for (int mf = 0; mf < 2; mf++) {
        int mr0 = mBase + wm * 32 + mf * 16 + (lane >> 2);
        int mr1 = mr0 + 8;
        int sa0 = mr0 >> 2, h0 = mr0 & 3;
        int sa1 = mr1 >> 2, h1 = mr1 & 3;
        bool ok0 = sa0 < salcnt, ok1 = sa1 < salcnt;
        size_t id0 = 0, id1 = 0;
        float inv0 = 0.f, inv1 = 0.f;
        if (ok0) { id0 = (size_t)g_idx[salst + sa0] * NH + 4 * g + h0; inv0 = g_inv[id0]; }
        if (ok1) { id1 = (size_t)g_idx[salst + sa1] * NH + 4 * g + h1; inv1 = g_inv[id1]; }
#pragma unroll
        for (int nf = 0; nf < 4; nf++) {
            int dcol = wn * 32 + nf * 8 + (lane & 3) * 2;
            float* c = acc[mf][nf];
            if (ok0) *(float2*)(outc + id0 * HD + dcol) = make_float2(inv0 * c[0], inv0 * c[1]);
            if (ok1) *(float2*)(outc + id1 * HD + dcol) = make_float2(inv1 * c[2], inv1 * c[3]);
        }
    }
}

// ---------------- K3: per-row cosine similarity ----------------
__global__ void __launch_bounds__(512) k_cos(const float* __restrict__ cc, const float* __restrict__ outc,
                                             float* __restrict__ cosv) {
    const int tid = threadIdx.x, wid = tid >> 5, lane = tid & 31;
    size_t base = (size_t)blockIdx.x * (NH * HD);
    const float4* a4 = (const float4*)(cc + base);
    const float4* b4 = (const float4*)(outc + base);
    float ab = 0.f, aa = 0.f, bb = 0.f;
#pragma unroll
    for (int j = 0; j < 2; j++) {
        float4 x = a4[tid + j * 512], y = b4[tid + j * 512];
        ab += x.x * y.x + x.y * y.y + x.z * y.z + x.w * y.w;
        aa += x.x * x.x + x.y * x.y + x.z * x.z + x.w * x.w;
        bb += y.x * y.x + y.y * y.y + y.z * y.z + y.w * y.w;
    }
#pragma unroll
    for (int o = 16; o; o >>= 1) {
        ab += __shfl_xor_sync(0xffffffffu, ab, o);
        aa += __shfl_xor_sync(0xffffffffu, aa, o);
        bb += __shfl_xor_sync(0xffffffffu, bb, o);
    }
    __shared__ float sh[3][16];
    if (lane == 0) { sh[0][wid] = ab; sh[1][wid] = aa; sh[2][wid] = bb; }
    __syncthreads();
    if (tid < 32) {
        float a2 = (tid < 16) ? sh[0][tid] : 0.f;
        float b2 = (tid < 16) ? sh[1][tid] : 0.f;
        float c2 = (tid < 16) ? sh[2][tid] : 0.f;
#pragma unroll
        for (int o = 8; o; o >>= 1) {
            a2 += __shfl_xor_sync(0xffffffffu, a2, o);
            b2 += __shfl_xor_sync(0xffffffffu, b2, o);
            c2 += __shfl_xor_sync(0xffffffffu, c2, o);
        }
        if (tid == 0)
            cosv[blockIdx.x] = a2 / (sqrtf(b2) * sqrtf(c2) + 1e-8f);
    }
}

// ---------------- launch ----------------
extern "C" void kernel_launch(void* const* d_in, const int* in_sizes, int n_in,
                              void* d_out, int out_size) {
    const float* q       = (const float*)d_in[0];
    const float* k       = (const float*)d_in[1];
    const float* v       = (const float*)d_in[2];
    const float* v_cache = (const float*)d_in[3];
    const float* c_cache = (const float*)d_in[4];
    const void*  idx     = d_in[5];
    const void*  cu      = d_in[6];

    float* outc = (float*)d_out;
    float* cosv = outc + (size_t)(out_size - TT);

    cudaFuncSetAttribute(k_qk,  cudaFuncAttributeMaxDynamicSharedMemorySize, 98304);
    cudaFuncSetAttribute(k_pv,  cudaFuncAttributeMaxDynamicSharedMemorySize, 98304);
    cudaFuncSetAttribute(k_pre, cudaFuncAttributeMaxDynamicSharedMemorySize, 16512);

    k_prep<<<1, 256>>>(idx, cu);
    k_pre<<<CVT_BLKS + VN_BLKS + VD_BLKS, 256, 16512>>>(k, v, v_cache);
    k_qk<<<dim3(32, 32), 256, 98304>>>(q, c_cache, outc);
    k_pv<<<dim3(8, 32), 256, 98304>>>(outc);
    k_cos<<<TT, 512>>>(c_cache, outc, cosv);
}